// round 3
// baseline (speedup 1.0000x reference)
#include <cuda_runtime.h>
#include <math.h>

// ---------------- problem constants ----------------
#define TOK   100352          // 32 * 3136 tokens
#define NWIN  2048            // 32 * 64 windows (b' dim)
#define FLATQ 38535168        // 384 * 100352 (q/k/v channel-slice stride in flat space)

// ---------------- scratch (device globals; no allocations) ----------------
__device__ float g_h   [(size_t)TOK * 384];    // LN output (reused for LN2)
__device__ float g_qkv [(size_t)TOK * 1152];   // gelu(qkv)
__device__ float g_attn[(size_t)TOK * 384];    // attention output (b'-ordered)
__device__ float g_proj[(size_t)TOK * 384];    // gelu(att proj)
__device__ float g_x2  [(size_t)TOK * 384];    // x + attention branch
__device__ float g_fc1 [(size_t)TOK * 1536];   // gelu(fc1)

// ---------------- helpers ----------------
__device__ __forceinline__ float gelu_f(float v) {
    return 0.5f * v * (1.0f + erff(v * 0.70710678118654752f));
}

// ============================================================
// 1) LayerNorm (+ optional shift-roll + window partition)
//    block = one output row (384 cols), 128 threads x 3 elems
// ============================================================
template<bool WINDOW>
__global__ void ln_kernel(const float* __restrict__ x,
                          const float* __restrict__ gamma,
                          const float* __restrict__ beta,
                          float* __restrict__ out)
{
    int r = blockIdx.x;                    // destination row
    size_t src;
    if (WINDOW) {
        int bw = r / 49, l = r % 49;       // window index (b*64 + w), pos in window
        int b = bw >> 6, w = bw & 63;
        int i = (w >> 3) * 7 + l / 7;      // shifted-grid coords
        int j = (w & 7)  * 7 + l % 7;
        int si = (i + 3) % 56;             // roll(-3): h[i] = x[(i+3)%56]
        int sj = (j + 3) % 56;
        src = ((size_t)b * 3136 + si * 56 + sj) * 384;
    } else {
        src = (size_t)r * 384;
    }
    int t = threadIdx.x;                   // 128 threads
    float v0 = x[src + t];
    float v1 = x[src + t + 128];
    float v2 = x[src + t + 256];
    float s  = v0 + v1 + v2;
    float sq = v0 * v0 + v1 * v1 + v2 * v2;
    #pragma unroll
    for (int o = 16; o > 0; o >>= 1) {
        s  += __shfl_xor_sync(0xffffffffu, s,  o);
        sq += __shfl_xor_sync(0xffffffffu, sq, o);
    }
    __shared__ float sa[4], sb[4];
    int wi = t >> 5;
    if ((t & 31) == 0) { sa[wi] = s; sb[wi] = sq; }
    __syncthreads();
    s  = sa[0] + sa[1] + sa[2] + sa[3];
    sq = sb[0] + sb[1] + sb[2] + sb[3];
    float mu  = s  * (1.0f / 384.0f);
    float var = sq * (1.0f / 384.0f) - mu * mu;
    float inv = rsqrtf(var + 1e-3f);
    size_t o0 = (size_t)r * 384;
    out[o0 + t]       = (v0 - mu) * inv * gamma[t]       + beta[t];
    out[o0 + t + 128] = (v1 - mu) * inv * gamma[t + 128] + beta[t + 128];
    out[o0 + t + 256] = (v2 - mu) * inv * gamma[t + 256] + beta[t + 256];
}

// ============================================================
// 2) SGEMM: C = act(A[M,K] @ W[K,N] + bias) (+ optional residual R)
//    128x128 block tile, 256 threads, 8x8 micro tile, BK=16
// ============================================================
template<bool GELU, bool ADD>
__global__ __launch_bounds__(256)
void gemm_kernel(const float* __restrict__ A, const float* __restrict__ W,
                 const float* __restrict__ bias, const float* __restrict__ R,
                 float* __restrict__ C, int M, int N, int K)
{
    __shared__ float As[16][132];   // A tile transposed: As[k][m]
    __shared__ float Bs[16][128];   // B tile: Bs[k][n]
    int tid = threadIdx.x;
    int m0 = blockIdx.y * 128;
    int n0 = blockIdx.x * 128;
    int ty = tid >> 4, tx = tid & 15;

    float acc[8][8];
    #pragma unroll
    for (int i = 0; i < 8; i++)
        #pragma unroll
        for (int j = 0; j < 8; j++) acc[i][j] = 0.0f;

    for (int k0 = 0; k0 < K; k0 += 16) {
        // load A tile: 128 rows x 16 k (512 float4)
        #pragma unroll
        for (int i = 0; i < 2; i++) {
            int lin = tid + i * 256;
            int row = lin >> 2, kq = lin & 3;
            float4 v = *(const float4*)(A + (size_t)(m0 + row) * K + k0 + kq * 4);
            As[kq * 4 + 0][row] = v.x;
            As[kq * 4 + 1][row] = v.y;
            As[kq * 4 + 2][row] = v.z;
            As[kq * 4 + 3][row] = v.w;
        }
        // load B tile: 16 k x 128 n (512 float4)
        #pragma unroll
        for (int i = 0; i < 2; i++) {
            int lin = tid + i * 256;
            int row = lin >> 5, nq = lin & 31;
            *(float4*)(&Bs[row][nq * 4]) =
                *(const float4*)(W + (size_t)(k0 + row) * N + n0 + nq * 4);
        }
        __syncthreads();
        #pragma unroll
        for (int k = 0; k < 16; k++) {
            float a[8], b[8];
            *(float4*)&a[0] = *(const float4*)&As[k][ty * 8];
            *(float4*)&a[4] = *(const float4*)&As[k][ty * 8 + 4];
            *(float4*)&b[0] = *(const float4*)&Bs[k][tx * 8];
            *(float4*)&b[4] = *(const float4*)&Bs[k][tx * 8 + 4];
            #pragma unroll
            for (int i = 0; i < 8; i++)
                #pragma unroll
                for (int j = 0; j < 8; j++)
                    acc[i][j] += a[i] * b[j];
        }
        __syncthreads();
    }

    #pragma unroll
    for (int i = 0; i < 8; i++) {
        int m = m0 + ty * 8 + i;
        size_t off = (size_t)m * N + n0 + tx * 8;
        float o[8];
        #pragma unroll
        for (int j = 0; j < 8; j++) {
            float v = acc[i][j] + bias[n0 + tx * 8 + j];
            if (GELU) v = gelu_f(v);
            if (ADD)  v += R[off + j];
            o[j] = v;
        }
        *(float4*)(C + off)     = *(float4*)&o[0];
        *(float4*)(C + off + 4) = *(float4*)&o[4];
    }
}

// ============================================================
// 3) Fused windowed attention, faithful channel-major reshape.
//    One block per (b', head). q/k/v gathered as a strided column.
// ============================================================
__global__ __launch_bounds__(256)
void attn_kernel(const float* __restrict__ qkv, const float* __restrict__ bt,
                 float* __restrict__ out)
{
    __shared__ float sQ[1568], sK[1568], sV[1568];   // 49 x 32 each
    __shared__ float sS[2401];                       // 49 x 49 scores
    __shared__ int   lab[49];
    int h  = blockIdx.x;     // 0..11
    int bp = blockIdx.y;     // 0..2047 (b' from channel-major reshape)
    int tid = threadIdx.x;
    int base = bp * 18816 + h * 1568;

    for (int idx = tid; idx < 1568; idx += 256) {
        int f = base + idx;
        int col = f / TOK, row = f - col * TOK;
        sQ[idx] = qkv[(size_t)row * 1152 + col];
        f += FLATQ; col = f / TOK; row = f - col * TOK;
        sK[idx] = qkv[(size_t)row * 1152 + col];
        f += FLATQ; col = f / TOK; row = f - col * TOK;
        sV[idx] = qkv[(size_t)row * 1152 + col];
    }
    if (tid < 49) {
        int w = bp & 63;
        int i = (w >> 3) * 7 + tid / 7;
        int j = (w & 7)  * 7 + tid % 7;
        int ri = (i < 7) ? 0 : (i < 10) ? 1 : (i >= 53) ? 2 : 3;
        int cj = (j < 7) ? 0 : (j < 10) ? 1 : (j >= 53) ? 2 : 3;
        lab[tid] = (ri < 3 && cj < 3) ? ri * 3 + cj : 0;
    }
    __syncthreads();

    // scores + relative-position bias + shift mask
    for (int p = tid; p < 2401; p += 256) {
        int l = p / 49, m = p - l * 49;
        float acc = 0.0f;
        #pragma unroll
        for (int c = 0; c < 32; c++) acc += sQ[l * 32 + c] * sK[m * 32 + c];
        int rel = 13 * ((m % 7 - l % 7 + 6) + (m / 7 - l / 7 + 6));
        acc += bt[rel * 12 + h];
        if (lab[l] != lab[m]) acc -= 100.0f;
        sS[p] = acc;
    }
    __syncthreads();

    // softmax per row (49 rows)
    if (tid < 49) {
        float mx = -1e30f;
        #pragma unroll 7
        for (int m = 0; m < 49; m++) mx = fmaxf(mx, sS[tid * 49 + m]);
        float sum = 0.0f;
        #pragma unroll 7
        for (int m = 0; m < 49; m++) {
            float e = expf(sS[tid * 49 + m] - mx);
            sS[tid * 49 + m] = e;
            sum += e;
        }
        float inv = 1.0f / sum;
        #pragma unroll 7
        for (int m = 0; m < 49; m++) sS[tid * 49 + m] *= inv;
    }
    __syncthreads();

    // P @ V, write [b', l, h*32+c]
    for (int p = tid; p < 1568; p += 256) {
        int l = p >> 5, c = p & 31;
        float acc = 0.0f;
        #pragma unroll 7
        for (int m = 0; m < 49; m++) acc += sS[l * 49 + m] * sV[m * 32 + c];
        out[((size_t)bp * 49 + l) * 384 + h * 32 + c] = acc;
    }
}

// ============================================================
// 5) window reverse + roll(+3,+3) + residual add
//    block = one output token, 96 threads x float4
// ============================================================
__global__ void wrev_add_kernel(const float* __restrict__ x,
                                const float* __restrict__ proj,
                                float* __restrict__ x2)
{
    int t = blockIdx.x;                    // token
    int b = t / 3136, ij = t - b * 3136;
    int i = ij / 56, j = ij - i * 56;
    int hh = (i + 53) % 56;                // roll(+3): final[i] = rev[(i-3)%56]
    int ww = (j + 53) % 56;
    int bw = b * 64 + (hh / 7) * 8 + (ww / 7);
    int l  = (hh % 7) * 7 + (ww % 7);
    const float4* xp = (const float4*)(x    + (size_t)t * 384);
    const float4* pp = (const float4*)(proj + ((size_t)bw * 49 + l) * 384);
    float4*       op = (float4*)(x2 + (size_t)t * 384);
    int c = threadIdx.x;                   // 96
    float4 a = xp[c], p = pp[c];
    float4 r; r.x = a.x + p.x; r.y = a.y + p.y; r.z = a.z + p.z; r.w = a.w + p.w;
    op[c] = r;
}

// ============================================================
extern "C" void kernel_launch(void* const* d_in, const int* in_sizes, int n_in,
                              void* d_out, int out_size)
{
    (void)in_sizes; (void)n_in; (void)out_size;
    const float* x     = (const float*)d_in[0];
    const float* gamma = (const float*)d_in[1];
    const float* beta  = (const float*)d_in[2];
    const float* w_qkv = (const float*)d_in[3];
    const float* b_qkv = (const float*)d_in[4];
    const float* bt    = (const float*)d_in[5];
    const float* w_att = (const float*)d_in[6];
    const float* b_att = (const float*)d_in[7];
    const float* w_fc1 = (const float*)d_in[8];
    const float* b_fc1 = (const float*)d_in[9];
    const float* w_fc2 = (const float*)d_in[10];
    const float* b_fc2 = (const float*)d_in[11];
    float* out = (float*)d_out;

    float *h_p, *qkv_p, *attn_p, *proj_p, *x2_p, *fc1_p;
    cudaGetSymbolAddress((void**)&h_p,    g_h);
    cudaGetSymbolAddress((void**)&qkv_p,  g_qkv);
    cudaGetSymbolAddress((void**)&attn_p, g_attn);
    cudaGetSymbolAddress((void**)&proj_p, g_proj);
    cudaGetSymbolAddress((void**)&x2_p,   g_x2);
    cudaGetSymbolAddress((void**)&fc1_p,  g_fc1);

    // attention branch
    ln_kernel<true><<<TOK, 128>>>(x, gamma, beta, h_p);
    gemm_kernel<true,  false><<<dim3(9, 784),  256>>>(h_p,    w_qkv, b_qkv, nullptr, qkv_p, TOK, 1152, 384);
    attn_kernel<<<dim3(12, NWIN), 256>>>(qkv_p, bt, attn_p);
    gemm_kernel<true,  false><<<dim3(3, 784),  256>>>(attn_p, w_att, b_att, nullptr, proj_p, TOK, 384, 384);
    wrev_add_kernel<<<TOK, 96>>>(x, proj_p, x2_p);

    // MLP branch
    ln_kernel<false><<<TOK, 128>>>(x2_p, gamma, beta, h_p);
    gemm_kernel<true,  false><<<dim3(12, 784), 256>>>(h_p,   w_fc1, b_fc1, nullptr, fc1_p, TOK, 1536, 384);
    gemm_kernel<false, true ><<<dim3(3, 784),  256>>>(fc1_p, w_fc2, b_fc2, x2_p,    out,   TOK, 384, 1536);
}

// round 7
// speedup vs baseline: 1.7223x; 1.7223x over previous
#include <cuda_runtime.h>
#include <cuda_bf16.h>
#include <math.h>
#include <stdint.h>

// ---------------- problem constants ----------------
#define TOK   100352          // 32 * 3136 tokens
#define NWIN  2048            // 32 * 64 windows (b' dim)
#define FLATQ 38535168        // 384 * 100352 (q/k/v channel-slice stride in flat space)

// ---------------- scratch (device globals; no allocations) ----------------
__device__ float g_h   [(size_t)TOK * 384];    // LN output (reused for LN2)
__device__ float g_qkv [(size_t)TOK * 1152];   // gelu(qkv)
__device__ float g_attn[(size_t)TOK * 384];    // attention output (b'-ordered)
__device__ float g_proj[(size_t)TOK * 384];    // gelu(att proj)
__device__ float g_x2  [(size_t)TOK * 384];    // x + attention branch
__device__ float g_fc1 [(size_t)TOK * 1536];   // gelu(fc1)

// transposed + bf16-split weights: Wt[n*K + k] = W[k*N + n]
__device__ __nv_bfloat16 g_wqkv_h[1152 * 384], g_wqkv_l[1152 * 384];
__device__ __nv_bfloat16 g_watt_h[384  * 384], g_watt_l[384  * 384];
__device__ __nv_bfloat16 g_wfc1_h[1536 * 384], g_wfc1_l[1536 * 384];
__device__ __nv_bfloat16 g_wfc2_h[384 * 1536], g_wfc2_l[384 * 1536];

// ---------------- helpers ----------------
__device__ __forceinline__ float gelu_f(float v) {
    return 0.5f * v * (1.0f + erff(v * 0.70710678118654752f));
}

__device__ __forceinline__ uint32_t smem_u32(const void* p) {
    uint32_t a;
    asm("{ .reg .u64 t; cvta.to.shared.u64 t, %1; cvt.u32.u64 %0, t; }" : "=r"(a) : "l"(p));
    return a;
}

__device__ __forceinline__ uint32_t packbf(__nv_bfloat16 a, __nv_bfloat16 b) {
    __nv_bfloat162 t(a, b);   // a -> low half (element k), b -> high (k+1)
    return *reinterpret_cast<uint32_t*>(&t);
}

__device__ __forceinline__ void ldm_x4(uint32_t& r0, uint32_t& r1,
                                       uint32_t& r2, uint32_t& r3, uint32_t addr) {
    asm volatile("ldmatrix.sync.aligned.m8n8.x4.shared.b16 {%0,%1,%2,%3}, [%4];"
                 : "=r"(r0), "=r"(r1), "=r"(r2), "=r"(r3) : "r"(addr));
}

__device__ __forceinline__ void mma_bf16(float* d, const uint32_t* a, const uint32_t* b) {
    asm volatile(
        "mma.sync.aligned.m16n8k16.row.col.f32.bf16.bf16.f32 "
        "{%0,%1,%2,%3}, {%4,%5,%6,%7}, {%8,%9}, {%0,%1,%2,%3};"
        : "+f"(d[0]), "+f"(d[1]), "+f"(d[2]), "+f"(d[3])
        : "r"(a[0]), "r"(a[1]), "r"(a[2]), "r"(a[3]), "r"(b[0]), "r"(b[1]));
}

// ============================================================
// 0) weight prep: transpose + bf16 hi/lo split
// ============================================================
__global__ void prep_w(const float* __restrict__ W, __nv_bfloat16* __restrict__ Th,
                       __nv_bfloat16* __restrict__ Tl, int K, int N)
{
    int idx = blockIdx.x * 256 + threadIdx.x;
    if (idx >= K * N) return;
    int n = idx / K, k = idx - n * K;
    float v = __ldg(W + (size_t)k * N + n);
    __nv_bfloat16 h = __float2bfloat16(v);
    Th[idx] = h;
    Tl[idx] = __float2bfloat16(v - __bfloat162float(h));
}

// ============================================================
// 1) LayerNorm (+ optional shift-roll + window partition)
// ============================================================
template<bool WINDOW>
__global__ void ln_kernel(const float* __restrict__ x,
                          const float* __restrict__ gamma,
                          const float* __restrict__ beta,
                          float* __restrict__ out)
{
    int r = blockIdx.x;
    size_t src;
    if (WINDOW) {
        int bw = r / 49, l = r % 49;
        int b = bw >> 6, w = bw & 63;
        int i = (w >> 3) * 7 + l / 7;
        int j = (w & 7)  * 7 + l % 7;
        int si = (i + 3) % 56;
        int sj = (j + 3) % 56;
        src = ((size_t)b * 3136 + si * 56 + sj) * 384;
    } else {
        src = (size_t)r * 384;
    }
    int t = threadIdx.x;
    float v0 = x[src + t];
    float v1 = x[src + t + 128];
    float v2 = x[src + t + 256];
    float s  = v0 + v1 + v2;
    float sq = v0 * v0 + v1 * v1 + v2 * v2;
    #pragma unroll
    for (int o = 16; o > 0; o >>= 1) {
        s  += __shfl_xor_sync(0xffffffffu, s,  o);
        sq += __shfl_xor_sync(0xffffffffu, sq, o);
    }
    __shared__ float sa[4], sb[4];
    int wi = t >> 5;
    if ((t & 31) == 0) { sa[wi] = s; sb[wi] = sq; }
    __syncthreads();
    s  = sa[0] + sa[1] + sa[2] + sa[3];
    sq = sb[0] + sb[1] + sb[2] + sb[3];
    float mu  = s  * (1.0f / 384.0f);
    float var = sq * (1.0f / 384.0f) - mu * mu;
    float inv = rsqrtf(var + 1e-3f);
    size_t o0 = (size_t)r * 384;
    out[o0 + t]       = (v0 - mu) * inv * gamma[t]       + beta[t];
    out[o0 + t + 128] = (v1 - mu) * inv * gamma[t + 128] + beta[t + 128];
    out[o0 + t + 256] = (v2 - mu) * inv * gamma[t + 256] + beta[t + 256];
}

// ============================================================
// 2) mma.sync bf16-split GEMM:
//    C = act(A[M,K] @ Wt^T + bias) (+ residual)
//    A fp32 row-major; Wt bf16 [N,K] hi/lo split.
//    CTA 128x128, BK=32, 8 warps (4m x 2n), warp 32x64.
//    3-term split: Ah*Bh + Al*Bh + Ah*Bl (fp32 accum).
// ============================================================
#define APAD 40   // bf16 elems per smem row (80B stride, conflict-free)

template<bool GELU, bool ADD>
__global__ __launch_bounds__(256)
void tc_gemm(const float* __restrict__ A,
             const __nv_bfloat16* __restrict__ Bh,
             const __nv_bfloat16* __restrict__ Bl,
             const float* __restrict__ bias, const float* __restrict__ R,
             float* __restrict__ C, int K, int N)
{
    __shared__ __nv_bfloat16 Ash[128][APAD], Asl[128][APAD];
    __shared__ __nv_bfloat16 Bsh[128][APAD], Bsl[128][APAD];

    int tid  = threadIdx.x;
    int wid  = tid >> 5;
    int lane = tid & 31;
    int m0 = blockIdx.y * 128;
    int n0 = blockIdx.x * 128;

    int mw = (wid >> 1) * 32;     // warp m offset in tile
    int nw = (wid & 1)  * 64;     // warp n offset in tile

    float acc[2][8][4];
    #pragma unroll
    for (int i = 0; i < 2; i++)
        #pragma unroll
        for (int j = 0; j < 8; j++)
            #pragma unroll
            for (int q = 0; q < 4; q++) acc[i][j][q] = 0.0f;

    // ldmatrix base addresses (per lane)
    // A: lanes 0-7 rows0-7/k0, 8-15 rows8-15/k0, 16-23 rows0-7/k+16B, 24-31 rows8-15/k+16B
    uint32_t aBh = smem_u32(&Ash[0][0]) + (uint32_t)((mw + (lane & 15)) * (APAD * 2)) + ((lane >> 4) << 4);
    uint32_t aBl = smem_u32(&Asl[0][0]) + (uint32_t)((mw + (lane & 15)) * (APAD * 2)) + ((lane >> 4) << 4);
    // B: lanes 0-7 n0-7/k0, 8-15 n0-7/k+16B, 16-23 n8-15/k0, 24-31 n8-15/k+16B
    uint32_t bRow = (uint32_t)(nw + ((lane >> 4) << 3) + (lane & 7)) * (APAD * 2) + (((lane >> 3) & 1) << 4);
    uint32_t bBh = smem_u32(&Bsh[0][0]) + bRow;
    uint32_t bBl = smem_u32(&Bsl[0][0]) + bRow;

    for (int k0 = 0; k0 < K; k0 += 32) {
        // ---- A tile: 128 rows x 32 k fp32 -> bf16 hi/lo ----
        #pragma unroll
        for (int i = 0; i < 4; i++) {
            int idx = tid + (i << 8);           // 0..1023
            int row = idx >> 3, q = idx & 7;    // k = 4q
            float4 v = *(const float4*)(A + (size_t)(m0 + row) * K + k0 + (q << 2));
            __nv_bfloat16 h0 = __float2bfloat16(v.x);
            __nv_bfloat16 h1 = __float2bfloat16(v.y);
            __nv_bfloat16 h2 = __float2bfloat16(v.z);
            __nv_bfloat16 h3 = __float2bfloat16(v.w);
            *(uint2*)&Ash[row][q << 2] = make_uint2(packbf(h0, h1), packbf(h2, h3));
            __nv_bfloat16 l0 = __float2bfloat16(v.x - __bfloat162float(h0));
            __nv_bfloat16 l1 = __float2bfloat16(v.y - __bfloat162float(h1));
            __nv_bfloat16 l2 = __float2bfloat16(v.z - __bfloat162float(h2));
            __nv_bfloat16 l3 = __float2bfloat16(v.w - __bfloat162float(h3));
            *(uint2*)&Asl[row][q << 2] = make_uint2(packbf(l0, l1), packbf(l2, l3));
        }
        // ---- B tiles: 128 n-rows x 32 k bf16 (pre-split) ----
        #pragma unroll
        for (int i = 0; i < 2; i++) {
            int idx = tid + (i << 8);           // 0..511
            int row = idx >> 2, q = idx & 3;    // k = 8q (16B)
            size_t goff = (size_t)(n0 + row) * K + k0 + (q << 3);
            *(uint4*)&Bsh[row][q << 3] = *(const uint4*)(Bh + goff);
            *(uint4*)&Bsl[row][q << 3] = *(const uint4*)(Bl + goff);
        }
        __syncthreads();

        #pragma unroll
        for (int s = 0; s < 2; s++) {
            uint32_t ko = (uint32_t)(s << 5);   // 16 bf16 = 32B per k16 step
            uint32_t afh[2][4], afl[2][4], bfh[8][2], bfl[8][2];
            #pragma unroll
            for (int mt = 0; mt < 2; mt++) {
                ldm_x4(afh[mt][0], afh[mt][1], afh[mt][2], afh[mt][3],
                       aBh + mt * (16 * APAD * 2) + ko);
                ldm_x4(afl[mt][0], afl[mt][1], afl[mt][2], afl[mt][3],
                       aBl + mt * (16 * APAD * 2) + ko);
            }
            #pragma unroll
            for (int np = 0; np < 4; np++) {
                ldm_x4(bfh[2 * np][0], bfh[2 * np][1], bfh[2 * np + 1][0], bfh[2 * np + 1][1],
                       bBh + np * (16 * APAD * 2) + ko);
                ldm_x4(bfl[2 * np][0], bfl[2 * np][1], bfl[2 * np + 1][0], bfl[2 * np + 1][1],
                       bBl + np * (16 * APAD * 2) + ko);
            }
            #pragma unroll
            for (int mt = 0; mt < 2; mt++)
                #pragma unroll
                for (int nt = 0; nt < 8; nt++) {
                    mma_bf16(acc[mt][nt], afh[mt], bfh[nt]);
                    mma_bf16(acc[mt][nt], afl[mt], bfh[nt]);
                    mma_bf16(acc[mt][nt], afh[mt], bfl[nt]);
                }
        }
        __syncthreads();
    }

    // ---- epilogue ----
    int mrow = m0 + mw + (lane >> 2);
    int ncol = n0 + nw + ((lane & 3) << 1);
    #pragma unroll
    for (int mt = 0; mt < 2; mt++) {
        #pragma unroll
        for (int nt = 0; nt < 8; nt++) {
            int n = ncol + nt * 8;
            float b0 = __ldg(bias + n), b1 = __ldg(bias + n + 1);
            #pragma unroll
            for (int half = 0; half < 2; half++) {
                int m = mrow + mt * 16 + half * 8;
                float v0 = acc[mt][nt][half * 2 + 0] + b0;
                float v1 = acc[mt][nt][half * 2 + 1] + b1;
                if (GELU) { v0 = gelu_f(v0); v1 = gelu_f(v1); }
                size_t off = (size_t)m * N + n;
                if (ADD) {
                    float2 rv = *(const float2*)(R + off);
                    v0 += rv.x; v1 += rv.y;
                }
                float2 o; o.x = v0; o.y = v1;
                *(float2*)(C + off) = o;
            }
        }
    }
}

// ============================================================
// 3) Fused windowed attention (faithful channel-major reshape)
// ============================================================
__global__ __launch_bounds__(256)
void attn_kernel(const float* __restrict__ qkv, const float* __restrict__ bt,
                 float* __restrict__ out)
{
    __shared__ float sQ[1568], sK[1568], sV[1568];
    __shared__ float sS[2401];
    __shared__ int   lab[49];
    int h  = blockIdx.x;
    int bp = blockIdx.y;
    int tid = threadIdx.x;
    int base = bp * 18816 + h * 1568;

    for (int idx = tid; idx < 1568; idx += 256) {
        int f = base + idx;
        int col = f / TOK, row = f - col * TOK;
        sQ[idx] = qkv[(size_t)row * 1152 + col];
        f += FLATQ; col = f / TOK; row = f - col * TOK;
        sK[idx] = qkv[(size_t)row * 1152 + col];
        f += FLATQ; col = f / TOK; row = f - col * TOK;
        sV[idx] = qkv[(size_t)row * 1152 + col];
    }
    if (tid < 49) {
        int w = bp & 63;
        int i = (w >> 3) * 7 + tid / 7;
        int j = (w & 7)  * 7 + tid % 7;
        int ri = (i < 7) ? 0 : (i < 10) ? 1 : (i >= 53) ? 2 : 3;
        int cj = (j < 7) ? 0 : (j < 10) ? 1 : (j >= 53) ? 2 : 3;
        lab[tid] = (ri < 3 && cj < 3) ? ri * 3 + cj : 0;
    }
    __syncthreads();

    for (int p = tid; p < 2401; p += 256) {
        int l = p / 49, m = p - l * 49;
        float acc = 0.0f;
        #pragma unroll
        for (int c = 0; c < 32; c++) acc += sQ[l * 32 + c] * sK[m * 32 + c];
        int rel = 13 * ((m % 7 - l % 7 + 6) + (m / 7 - l / 7 + 6));
        acc += bt[rel * 12 + h];
        if (lab[l] != lab[m]) acc -= 100.0f;
        sS[p] = acc;
    }
    __syncthreads();

    if (tid < 49) {
        float mx = -1e30f;
        #pragma unroll 7
        for (int m = 0; m < 49; m++) mx = fmaxf(mx, sS[tid * 49 + m]);
        float sum = 0.0f;
        #pragma unroll 7
        for (int m = 0; m < 49; m++) {
            float e = expf(sS[tid * 49 + m] - mx);
            sS[tid * 49 + m] = e;
            sum += e;
        }
        float inv = 1.0f / sum;
        #pragma unroll 7
        for (int m = 0; m < 49; m++) sS[tid * 49 + m] *= inv;
    }
    __syncthreads();

    for (int p = tid; p < 1568; p += 256) {
        int l = p >> 5, c = p & 31;
        float acc = 0.0f;
        #pragma unroll 7
        for (int m = 0; m < 49; m++) acc += sS[l * 49 + m] * sV[m * 32 + c];
        out[((size_t)bp * 49 + l) * 384 + h * 32 + c] = acc;
    }
}

// ============================================================
// 5) window reverse + roll(+3,+3) + residual add
// ============================================================
__global__ void wrev_add_kernel(const float* __restrict__ x,
                                const float* __restrict__ proj,
                                float* __restrict__ x2)
{
    int t = blockIdx.x;
    int b = t / 3136, ij = t - b * 3136;
    int i = ij / 56, j = ij - i * 56;
    int hh = (i + 53) % 56;
    int ww = (j + 53) % 56;
    int bw = b * 64 + (hh / 7) * 8 + (ww / 7);
    int l  = (hh % 7) * 7 + (ww % 7);
    const float4* xp = (const float4*)(x    + (size_t)t * 384);
    const float4* pp = (const float4*)(proj + ((size_t)bw * 49 + l) * 384);
    float4*       op = (float4*)(x2 + (size_t)t * 384);
    int c = threadIdx.x;
    float4 a = xp[c], p = pp[c];
    float4 r; r.x = a.x + p.x; r.y = a.y + p.y; r.z = a.z + p.z; r.w = a.w + p.w;
    op[c] = r;
}

// ============================================================
extern "C" void kernel_launch(void* const* d_in, const int* in_sizes, int n_in,
                              void* d_out, int out_size)
{
    (void)in_sizes; (void)n_in; (void)out_size;
    const float* x     = (const float*)d_in[0];
    const float* gamma = (const float*)d_in[1];
    const float* beta  = (const float*)d_in[2];
    const float* w_qkv = (const float*)d_in[3];
    const float* b_qkv = (const float*)d_in[4];
    const float* bt    = (const float*)d_in[5];
    const float* w_att = (const float*)d_in[6];
    const float* b_att = (const float*)d_in[7];
    const float* w_fc1 = (const float*)d_in[8];
    const float* b_fc1 = (const float*)d_in[9];
    const float* w_fc2 = (const float*)d_in[10];
    const float* b_fc2 = (const float*)d_in[11];
    float* out = (float*)d_out;

    float *h_p, *qkv_p, *attn_p, *proj_p, *x2_p, *fc1_p;
    cudaGetSymbolAddress((void**)&h_p,    g_h);
    cudaGetSymbolAddress((void**)&qkv_p,  g_qkv);
    cudaGetSymbolAddress((void**)&attn_p, g_attn);
    cudaGetSymbolAddress((void**)&proj_p, g_proj);
    cudaGetSymbolAddress((void**)&x2_p,   g_x2);
    cudaGetSymbolAddress((void**)&fc1_p,  g_fc1);

    __nv_bfloat16 *wqh, *wql, *wah, *wal, *w1h, *w1l, *w2h, *w2l;
    cudaGetSymbolAddress((void**)&wqh, g_wqkv_h);
    cudaGetSymbolAddress((void**)&wql, g_wqkv_l);
    cudaGetSymbolAddress((void**)&wah, g_watt_h);
    cudaGetSymbolAddress((void**)&wal, g_watt_l);
    cudaGetSymbolAddress((void**)&w1h, g_wfc1_h);
    cudaGetSymbolAddress((void**)&w1l, g_wfc1_l);
    cudaGetSymbolAddress((void**)&w2h, g_wfc2_h);
    cudaGetSymbolAddress((void**)&w2l, g_wfc2_l);

    // weight prep
    prep_w<<<(384 * 1152 + 255) / 256, 256>>>(w_qkv, wqh, wql, 384, 1152);
    prep_w<<<(384 * 384  + 255) / 256, 256>>>(w_att, wah, wal, 384, 384);
    prep_w<<<(384 * 1536 + 255) / 256, 256>>>(w_fc1, w1h, w1l, 384, 1536);
    prep_w<<<(1536 * 384 + 255) / 256, 256>>>(w_fc2, w2h, w2l, 1536, 384);

    // attention branch
    ln_kernel<true><<<TOK, 128>>>(x, gamma, beta, h_p);
    tc_gemm<true,  false><<<dim3(9, 784),  256>>>(h_p,    wqh, wql, b_qkv, nullptr, qkv_p, 384, 1152);
    attn_kernel<<<dim3(12, NWIN), 256>>>(qkv_p, bt, attn_p);
    tc_gemm<true,  false><<<dim3(3, 784),  256>>>(attn_p, wah, wal, b_att, nullptr, proj_p, 384, 384);
    wrev_add_kernel<<<TOK, 96>>>(x, proj_p, x2_p);

    // MLP branch
    ln_kernel<false><<<TOK, 128>>>(x2_p, gamma, beta, h_p);
    tc_gemm<true,  false><<<dim3(12, 784), 256>>>(h_p,   w1h, w1l, b_fc1, nullptr, fc1_p, 384, 1536);
    tc_gemm<false, true ><<<dim3(3, 784),  256>>>(fc1_p, w2h, w2l, b_fc2, x2_p,    out,   1536, 384);
}

// round 9
// speedup vs baseline: 1.7450x; 1.0131x over previous
#include <cuda_runtime.h>
#include <cuda_bf16.h>
#include <math.h>
#include <stdint.h>

// ---------------- problem constants ----------------
#define TOK   100352          // 32 * 3136 tokens
#define NWIN  2048            // 32 * 64 windows (b' dim)
#define FLATQ 38535168        // 384 * 100352 (q/k/v channel-slice stride in flat space)

// ---------------- scratch (device globals; no allocations) ----------------
__device__ __nv_bfloat16 g_lnh [(size_t)TOK * 384],  g_lnl [(size_t)TOK * 384];   // LN out split
__device__ float         g_qkvT[(size_t)1152 * TOK];                              // gelu(qkv) TRANSPOSED [col][tok]
__device__ __nv_bfloat16 g_atth[(size_t)TOK * 384],  g_attl[(size_t)TOK * 384];   // attn out split
__device__ float         g_proj[(size_t)TOK * 384];                               // gelu(att proj)
__device__ float         g_x2  [(size_t)TOK * 384];                               // x + attention branch
__device__ __nv_bfloat16 g_fc1h[(size_t)TOK * 1536], g_fc1l[(size_t)TOK * 1536];  // gelu(fc1) split

// transposed + bf16-split weights: Wt[n*K + k] = W[k*N + n]
__device__ __nv_bfloat16 g_wqkv_h[1152 * 384], g_wqkv_l[1152 * 384];
__device__ __nv_bfloat16 g_watt_h[384  * 384], g_watt_l[384  * 384];
__device__ __nv_bfloat16 g_wfc1_h[1536 * 384], g_wfc1_l[1536 * 384];
__device__ __nv_bfloat16 g_wfc2_h[384 * 1536], g_wfc2_l[384 * 1536];

// ---------------- helpers ----------------
__device__ __forceinline__ float gelu_f(float v) {
    return 0.5f * v * (1.0f + erff(v * 0.70710678118654752f));
}

__device__ __forceinline__ uint32_t smem_u32(const void* p) {
    uint32_t a;
    asm("{ .reg .u64 t; cvta.to.shared.u64 t, %1; cvt.u32.u64 %0, t; }" : "=r"(a) : "l"(p));
    return a;
}

__device__ __forceinline__ uint32_t packbf(__nv_bfloat16 a, __nv_bfloat16 b) {
    __nv_bfloat162 t(a, b);
    return *reinterpret_cast<uint32_t*>(&t);
}

__device__ __forceinline__ void ldm_x4(uint32_t& r0, uint32_t& r1,
                                       uint32_t& r2, uint32_t& r3, uint32_t addr) {
    asm volatile("ldmatrix.sync.aligned.m8n8.x4.shared.b16 {%0,%1,%2,%3}, [%4];"
                 : "=r"(r0), "=r"(r1), "=r"(r2), "=r"(r3) : "r"(addr));
}

__device__ __forceinline__ void mma_bf16(float* d, const uint32_t* a, const uint32_t* b) {
    asm volatile(
        "mma.sync.aligned.m16n8k16.row.col.f32.bf16.bf16.f32 "
        "{%0,%1,%2,%3}, {%4,%5,%6,%7}, {%8,%9}, {%0,%1,%2,%3};"
        : "+f"(d[0]), "+f"(d[1]), "+f"(d[2]), "+f"(d[3])
        : "r"(a[0]), "r"(a[1]), "r"(a[2]), "r"(a[3]), "r"(b[0]), "r"(b[1]));
}

__device__ __forceinline__ void cp16(uint32_t dst, const void* src) {
    asm volatile("cp.async.ca.shared.global [%0], [%1], 16;" :: "r"(dst), "l"(src));
}

// ============================================================
// 0) weight prep: transpose + bf16 hi/lo split
// ============================================================
__global__ void prep_w(const float* __restrict__ W, __nv_bfloat16* __restrict__ Th,
                       __nv_bfloat16* __restrict__ Tl, int K, int N)
{
    int idx = blockIdx.x * 256 + threadIdx.x;
    if (idx >= K * N) return;
    int n = idx / K, k = idx - n * K;
    float v = __ldg(W + (size_t)k * N + n);
    __nv_bfloat16 h = __float2bfloat16(v);
    Th[idx] = h;
    Tl[idx] = __float2bfloat16(v - __bfloat162float(h));
}

// ============================================================
// 1) LayerNorm (+ optional shift-roll + window partition), bf16 hi/lo out
// ============================================================
template<bool WINDOW>
__global__ void ln_kernel(const float* __restrict__ x,
                          const float* __restrict__ gamma,
                          const float* __restrict__ beta,
                          __nv_bfloat16* __restrict__ oh,
                          __nv_bfloat16* __restrict__ ol)
{
    int r = blockIdx.x;
    size_t src;
    if (WINDOW) {
        int bw = r / 49, l = r % 49;
        int b = bw >> 6, w = bw & 63;
        int i = (w >> 3) * 7 + l / 7;
        int j = (w & 7)  * 7 + l % 7;
        int si = (i + 3) % 56;
        int sj = (j + 3) % 56;
        src = ((size_t)b * 3136 + si * 56 + sj) * 384;
    } else {
        src = (size_t)r * 384;
    }
    int t = threadIdx.x;
    float v0 = x[src + t];
    float v1 = x[src + t + 128];
    float v2 = x[src + t + 256];
    float s  = v0 + v1 + v2;
    float sq = v0 * v0 + v1 * v1 + v2 * v2;
    #pragma unroll
    for (int o = 16; o > 0; o >>= 1) {
        s  += __shfl_xor_sync(0xffffffffu, s,  o);
        sq += __shfl_xor_sync(0xffffffffu, sq, o);
    }
    __shared__ float sa[4], sb[4];
    int wi = t >> 5;
    if ((t & 31) == 0) { sa[wi] = s; sb[wi] = sq; }
    __syncthreads();
    s  = sa[0] + sa[1] + sa[2] + sa[3];
    sq = sb[0] + sb[1] + sb[2] + sb[3];
    float mu  = s  * (1.0f / 384.0f);
    float var = sq * (1.0f / 384.0f) - mu * mu;
    float inv = rsqrtf(var + 1e-3f);
    size_t o0 = (size_t)r * 384;
    #pragma unroll
    for (int e = 0; e < 3; e++) {
        int c = t + e * 128;
        float v = (e == 0 ? v0 : e == 1 ? v1 : v2);
        float f = (v - mu) * inv * gamma[c] + beta[c];
        __nv_bfloat16 h = __float2bfloat16(f);
        oh[o0 + c] = h;
        ol[o0 + c] = __float2bfloat16(f - __bfloat162float(h));
    }
}

// ============================================================
// 2) mma.sync bf16-split GEMM, cp.async 2-stage pipeline.
//    C = act(A @ Wt^T + bias); A = Ah+Al bf16 [M,K]; Wt bf16 [N,K] hi/lo.
//    CTA 128x128, BK=32, 8 warps (4m x 2n), warp 32x64.
//    MODE 0: fp32 out + gelu
//    MODE 1: fp32 out TRANSPOSED [N][Mtot] + gelu (smem-staged)
//    MODE 2: bf16 hi/lo out + gelu
//    MODE 3: fp32 out + residual
// ============================================================
#define STAGE_BYTES 40960   // 4 buffers x 128 rows x 80B
#define GSMEM (2 * STAGE_BYTES)

template<int MODE>
__global__ __launch_bounds__(256)
void tc_gemm(const __nv_bfloat16* __restrict__ Ah_g,
             const __nv_bfloat16* __restrict__ Al_g,
             const __nv_bfloat16* __restrict__ Bh,
             const __nv_bfloat16* __restrict__ Bl,
             const float* __restrict__ bias, const float* __restrict__ R,
             float* __restrict__ C,
             __nv_bfloat16* __restrict__ Ch, __nv_bfloat16* __restrict__ Cl,
             int K, int N, int Mtot)
{
    extern __shared__ __align__(16) unsigned char dsm[];
    uint32_t smemBase = smem_u32(dsm);

    int tid  = threadIdx.x;
    int wid  = tid >> 5;
    int lane = tid & 31;
    int m0 = blockIdx.y * 128;
    int n0 = blockIdx.x * 128;
    int mw = (wid >> 1) * 32;
    int nw = (wid & 1)  * 64;

    float acc[2][8][4];
    #pragma unroll
    for (int i = 0; i < 2; i++)
        #pragma unroll
        for (int j = 0; j < 8; j++)
            #pragma unroll
            for (int q = 0; q < 4; q++) acc[i][j][q] = 0.0f;

    // ldmatrix per-lane offsets (80B row stride)
    uint32_t aOff = (uint32_t)((mw + (lane & 15)) * 80 + ((lane >> 4) << 4));
    uint32_t bOff = (uint32_t)((nw + ((lane >> 4) << 3) + (lane & 7)) * 80 + (((lane >> 3) & 1) << 4));

    int ntiles = K >> 5;

    // ---- stage loader: 8 cp.async per thread ----
    auto load_stage = [&](int s, int k0) {
        uint32_t sb = smemBase + s * STAGE_BYTES;
        #pragma unroll
        for (int i = 0; i < 2; i++) {
            int idx = tid + (i << 8);         // 0..511
            int row = idx >> 2, q = idx & 3;
            uint32_t d = (uint32_t)(row * 80 + (q << 4));
            size_t ga = (size_t)(m0 + row) * K + k0 + (q << 3);
            cp16(sb + d,         Ah_g + ga);
            cp16(sb + 10240 + d, Al_g + ga);
            size_t gb = (size_t)(n0 + row) * K + k0 + (q << 3);
            cp16(sb + 20480 + d, Bh + gb);
            cp16(sb + 30720 + d, Bl + gb);
        }
    };

    load_stage(0, 0);
    asm volatile("cp.async.commit_group;" ::: "memory");

    for (int t = 0; t < ntiles; t++) {
        if (t + 1 < ntiles) {
            load_stage((t + 1) & 1, (t + 1) << 5);
            asm volatile("cp.async.commit_group;" ::: "memory");
            asm volatile("cp.async.wait_group 1;" ::: "memory");
        } else {
            asm volatile("cp.async.wait_group 0;" ::: "memory");
        }
        __syncthreads();

        uint32_t sb = smemBase + (t & 1) * STAGE_BYTES;
        #pragma unroll
        for (int s = 0; s < 2; s++) {
            uint32_t ko = (uint32_t)(s << 5);   // 16 bf16 = 32B
            uint32_t afh[2][4], afl[2][4], bfh[8][2], bfl[8][2];
            #pragma unroll
            for (int mt = 0; mt < 2; mt++) {
                ldm_x4(afh[mt][0], afh[mt][1], afh[mt][2], afh[mt][3],
                       sb + aOff + mt * (16 * 80) + ko);
                ldm_x4(afl[mt][0], afl[mt][1], afl[mt][2], afl[mt][3],
                       sb + 10240 + aOff + mt * (16 * 80) + ko);
            }
            #pragma unroll
            for (int np = 0; np < 4; np++) {
                ldm_x4(bfh[2 * np][0], bfh[2 * np][1], bfh[2 * np + 1][0], bfh[2 * np + 1][1],
                       sb + 20480 + bOff + np * (16 * 80) + ko);
                ldm_x4(bfl[2 * np][0], bfl[2 * np][1], bfl[2 * np + 1][0], bfl[2 * np + 1][1],
                       sb + 30720 + bOff + np * (16 * 80) + ko);
            }
            #pragma unroll
            for (int mt = 0; mt < 2; mt++)
                #pragma unroll
                for (int nt = 0; nt < 8; nt++) {
                    mma_bf16(acc[mt][nt], afh[mt], bfh[nt]);
                    mma_bf16(acc[mt][nt], afl[mt], bfh[nt]);
                    mma_bf16(acc[mt][nt], afh[mt], bfl[nt]);
                }
        }
        __syncthreads();
    }

    // ---- epilogue ----
    if (MODE == 1) {
        // transposed store via smem staging, two 64-col passes
        float* st = (float*)dsm;   // [64][132]
        #pragma unroll
        for (int p = 0; p < 2; p++) {
            if ((wid & 1) == p) {
                int mL = mw + (lane >> 2);
                int nL = (lane & 3) << 1;
                #pragma unroll
                for (int mt = 0; mt < 2; mt++)
                    #pragma unroll
                    for (int nt = 0; nt < 8; nt++) {
                        int n = nL + nt * 8;
                        float b0 = __ldg(bias + n0 + p * 64 + n);
                        float b1 = __ldg(bias + n0 + p * 64 + n + 1);
                        #pragma unroll
                        for (int half = 0; half < 2; half++) {
                            int m = mL + mt * 16 + half * 8;
                            st[n * 132 + m]       = gelu_f(acc[mt][nt][half * 2 + 0] + b0);
                            st[(n + 1) * 132 + m] = gelu_f(acc[mt][nt][half * 2 + 1] + b1);
                        }
                    }
            }
            __syncthreads();
            #pragma unroll
            for (int i = 0; i < 8; i++) {
                int idx = tid + (i << 8);     // 0..2047
                int n = idx >> 5, mq = idx & 31;
                float4 v = *(float4*)&st[n * 132 + (mq << 2)];
                *(float4*)(C + (size_t)(n0 + p * 64 + n) * Mtot + m0 + (mq << 2)) = v;
            }
            __syncthreads();
        }
        return;
    }

    int mrow = m0 + mw + (lane >> 2);
    int ncol = n0 + nw + ((lane & 3) << 1);
    #pragma unroll
    for (int mt = 0; mt < 2; mt++) {
        #pragma unroll
        for (int nt = 0; nt < 8; nt++) {
            int n = ncol + nt * 8;
            float b0 = __ldg(bias + n), b1 = __ldg(bias + n + 1);
            #pragma unroll
            for (int half = 0; half < 2; half++) {
                int m = mrow + mt * 16 + half * 8;
                float v0 = acc[mt][nt][half * 2 + 0] + b0;
                float v1 = acc[mt][nt][half * 2 + 1] + b1;
                size_t off = (size_t)m * N + n;
                if (MODE == 0 || MODE == 2) { v0 = gelu_f(v0); v1 = gelu_f(v1); }
                if (MODE == 2) {
                    __nv_bfloat16 h0 = __float2bfloat16(v0);
                    __nv_bfloat16 h1 = __float2bfloat16(v1);
                    __nv_bfloat16 l0 = __float2bfloat16(v0 - __bfloat162float(h0));
                    __nv_bfloat16 l1 = __float2bfloat16(v1 - __bfloat162float(h1));
                    *(uint32_t*)(Ch + off) = packbf(h0, h1);
                    *(uint32_t*)(Cl + off) = packbf(l0, l1);
                } else {
                    if (MODE == 3) {
                        float2 rv = *(const float2*)(R + off);
                        v0 += rv.x; v1 += rv.y;
                    }
                    float2 o; o.x = v0; o.y = v1;
                    *(float2*)(C + off) = o;
                }
            }
        }
    }
}

// ============================================================
// 3) Fused windowed attention — coalesced gather from qkvT.
//    Flat channel-major index == linear index into [1152][TOK].
// ============================================================
__global__ __launch_bounds__(256)
void attn_kernel(const float* __restrict__ qkvT, const float* __restrict__ bt,
                 __nv_bfloat16* __restrict__ oh, __nv_bfloat16* __restrict__ ol)
{
    __shared__ float sQ[1568], sK[1568], sV[1568];
    __shared__ float sS[2401];
    __shared__ int   lab[49];
    int h  = blockIdx.x;
    int bp = blockIdx.y;
    int tid = threadIdx.x;
    size_t base = (size_t)bp * 18816 + h * 1568;

    for (int idx = tid; idx < 1568; idx += 256) {
        sQ[idx] = qkvT[base + idx];
        sK[idx] = qkvT[base + FLATQ + idx];
        sV[idx] = qkvT[base + 2 * (size_t)FLATQ + idx];
    }
    if (tid < 49) {
        int w = bp & 63;
        int i = (w >> 3) * 7 + tid / 7;
        int j = (w & 7)  * 7 + tid % 7;
        int ri = (i < 7) ? 0 : (i < 10) ? 1 : (i >= 53) ? 2 : 3;
        int cj = (j < 7) ? 0 : (j < 10) ? 1 : (j >= 53) ? 2 : 3;
        lab[tid] = (ri < 3 && cj < 3) ? ri * 3 + cj : 0;
    }
    __syncthreads();

    for (int p = tid; p < 2401; p += 256) {
        int l = p / 49, m = p - l * 49;
        float acc = 0.0f;
        #pragma unroll
        for (int c = 0; c < 32; c++) acc += sQ[l * 32 + c] * sK[m * 32 + c];
        int rel = 13 * ((m % 7 - l % 7 + 6) + (m / 7 - l / 7 + 6));
        acc += bt[rel * 12 + h];
        if (lab[l] != lab[m]) acc -= 100.0f;
        sS[p] = acc;
    }
    __syncthreads();

    if (tid < 49) {
        float mx = -1e30f;
        #pragma unroll 7
        for (int m = 0; m < 49; m++) mx = fmaxf(mx, sS[tid * 49 + m]);
        float sum = 0.0f;
        #pragma unroll 7
        for (int m = 0; m < 49; m++) {
            float e = expf(sS[tid * 49 + m] - mx);
            sS[tid * 49 + m] = e;
            sum += e;
        }
        float inv = 1.0f / sum;
        #pragma unroll 7
        for (int m = 0; m < 49; m++) sS[tid * 49 + m] *= inv;
    }
    __syncthreads();

    for (int p = tid; p < 1568; p += 256) {
        int l = p >> 5, c = p & 31;
        float acc = 0.0f;
        #pragma unroll 7
        for (int m = 0; m < 49; m++) acc += sS[l * 49 + m] * sV[m * 32 + c];
        size_t off = ((size_t)bp * 49 + l) * 384 + h * 32 + c;
        __nv_bfloat16 hh = __float2bfloat16(acc);
        oh[off] = hh;
        ol[off] = __float2bfloat16(acc - __bfloat162float(hh));
    }
}

// ============================================================
// 5) window reverse + roll(+3,+3) + residual add
// ============================================================
__global__ void wrev_add_kernel(const float* __restrict__ x,
                                const float* __restrict__ proj,
                                float* __restrict__ x2)
{
    int t = blockIdx.x;
    int b = t / 3136, ij = t - b * 3136;
    int i = ij / 56, j = ij - i * 56;
    int hh = (i + 53) % 56;
    int ww = (j + 53) % 56;
    int bw = b * 64 + (hh / 7) * 8 + (ww / 7);
    int l  = (hh % 7) * 7 + (ww % 7);
    const float4* xp = (const float4*)(x    + (size_t)t * 384);
    const float4* pp = (const float4*)(proj + ((size_t)bw * 49 + l) * 384);
    float4*       op = (float4*)(x2 + (size_t)t * 384);
    int c = threadIdx.x;
    float4 a = xp[c], p = pp[c];
    float4 r; r.x = a.x + p.x; r.y = a.y + p.y; r.z = a.z + p.z; r.w = a.w + p.w;
    op[c] = r;
}

// ============================================================
extern "C" void kernel_launch(void* const* d_in, const int* in_sizes, int n_in,
                              void* d_out, int out_size)
{
    (void)in_sizes; (void)n_in; (void)out_size;
    const float* x     = (const float*)d_in[0];
    const float* gamma = (const float*)d_in[1];
    const float* beta  = (const float*)d_in[2];
    const float* w_qkv = (const float*)d_in[3];
    const float* b_qkv = (const float*)d_in[4];
    const float* bt    = (const float*)d_in[5];
    const float* w_att = (const float*)d_in[6];
    const float* b_att = (const float*)d_in[7];
    const float* w_fc1 = (const float*)d_in[8];
    const float* b_fc1 = (const float*)d_in[9];
    const float* w_fc2 = (const float*)d_in[10];
    const float* b_fc2 = (const float*)d_in[11];
    float* out = (float*)d_out;

    __nv_bfloat16 *lnh, *lnl, *atth, *attl, *fc1h, *fc1l;
    float *qkvT, *proj, *x2;
    cudaGetSymbolAddress((void**)&lnh,  g_lnh);
    cudaGetSymbolAddress((void**)&lnl,  g_lnl);
    cudaGetSymbolAddress((void**)&qkvT, g_qkvT);
    cudaGetSymbolAddress((void**)&atth, g_atth);
    cudaGetSymbolAddress((void**)&attl, g_attl);
    cudaGetSymbolAddress((void**)&proj, g_proj);
    cudaGetSymbolAddress((void**)&x2,   g_x2);
    cudaGetSymbolAddress((void**)&fc1h, g_fc1h);
    cudaGetSymbolAddress((void**)&fc1l, g_fc1l);

    __nv_bfloat16 *wqh, *wql, *wah, *wal, *w1h, *w1l, *w2h, *w2l;
    cudaGetSymbolAddress((void**)&wqh, g_wqkv_h);
    cudaGetSymbolAddress((void**)&wql, g_wqkv_l);
    cudaGetSymbolAddress((void**)&wah, g_watt_h);
    cudaGetSymbolAddress((void**)&wal, g_watt_l);
    cudaGetSymbolAddress((void**)&w1h, g_wfc1_h);
    cudaGetSymbolAddress((void**)&w1l, g_wfc1_l);
    cudaGetSymbolAddress((void**)&w2h, g_wfc2_h);
    cudaGetSymbolAddress((void**)&w2l, g_wfc2_l);

    cudaFuncSetAttribute(tc_gemm<0>, cudaFuncAttributeMaxDynamicSharedMemorySize, GSMEM);
    cudaFuncSetAttribute(tc_gemm<1>, cudaFuncAttributeMaxDynamicSharedMemorySize, GSMEM);
    cudaFuncSetAttribute(tc_gemm<2>, cudaFuncAttributeMaxDynamicSharedMemorySize, GSMEM);
    cudaFuncSetAttribute(tc_gemm<3>, cudaFuncAttributeMaxDynamicSharedMemorySize, GSMEM);

    // weight prep
    prep_w<<<(384 * 1152 + 255) / 256, 256>>>(w_qkv, wqh, wql, 384, 1152);
    prep_w<<<(384 * 384  + 255) / 256, 256>>>(w_att, wah, wal, 384, 384);
    prep_w<<<(384 * 1536 + 255) / 256, 256>>>(w_fc1, w1h, w1l, 384, 1536);
    prep_w<<<(1536 * 384 + 255) / 256, 256>>>(w_fc2, w2h, w2l, 1536, 384);

    // attention branch
    ln_kernel<true><<<TOK, 128>>>(x, gamma, beta, lnh, lnl);
    tc_gemm<1><<<dim3(9, 784), 256, GSMEM>>>(lnh, lnl, wqh, wql, b_qkv, nullptr,
                                             qkvT, nullptr, nullptr, 384, 1152, TOK);
    attn_kernel<<<dim3(12, NWIN), 256>>>(qkvT, bt, atth, attl);
    tc_gemm<0><<<dim3(3, 784), 256, GSMEM>>>(atth, attl, wah, wal, b_att, nullptr,
                                             proj, nullptr, nullptr, 384, 384, TOK);
    wrev_add_kernel<<<TOK, 96>>>(x, proj, x2);

    // MLP branch
    ln_kernel<false><<<TOK, 128>>>(x2, gamma, beta, lnh, lnl);
    tc_gemm<2><<<dim3(12, 784), 256, GSMEM>>>(lnh, lnl, w1h, w1l, b_fc1, nullptr,
                                              nullptr, fc1h, fc1l, 384, 1536, TOK);
    tc_gemm<3><<<dim3(3, 784), 256, GSMEM>>>(fc1h, fc1l, w2h, w2l, b_fc2, x2,
                                             out, nullptr, nullptr, 1536, 384, TOK);
}

// round 10
// speedup vs baseline: 2.2622x; 1.2964x over previous
#include <cuda_runtime.h>
#include <cuda_fp16.h>
#include <math.h>
#include <stdint.h>

// ---------------- problem constants ----------------
#define TOK   100352          // 32 * 3136 tokens
#define NWIN  2048            // 32 * 64 windows (b' dim)
#define FLATQ 38535168        // 384 * 100352 (q/k/v channel-slice stride in flat space)

// ---------------- scratch (device globals; no allocations) ----------------
__device__ __half g_lnh [(size_t)TOK * 384];     // LN out (fp16)
__device__ float  g_qkvT[(size_t)1152 * TOK];    // gelu(qkv) TRANSPOSED [col][tok]
__device__ __half g_atth[(size_t)TOK * 384];     // attn out (fp16)
__device__ float  g_x2  [(size_t)TOK * 384];     // x + attention branch
__device__ __half g_fc1h[(size_t)TOK * 1536];    // gelu(fc1) (fp16)

// transposed + fp16-split weights: Wt[n*K + k] = W[k*N + n]
__device__ __half g_wqkv_h[1152 * 384], g_wqkv_l[1152 * 384];
__device__ __half g_watt_h[384  * 384], g_watt_l[384  * 384];
__device__ __half g_wfc1_h[1536 * 384], g_wfc1_l[1536 * 384];
__device__ __half g_wfc2_h[384 * 1536], g_wfc2_l[384 * 1536];

// ---------------- helpers ----------------
__device__ __forceinline__ float gelu_f(float v) {
    return 0.5f * v * (1.0f + erff(v * 0.70710678118654752f));
}

__device__ __forceinline__ uint32_t smem_u32(const void* p) {
    uint32_t a;
    asm("{ .reg .u64 t; cvta.to.shared.u64 t, %1; cvt.u32.u64 %0, t; }" : "=r"(a) : "l"(p));
    return a;
}

__device__ __forceinline__ void ldm_x4(uint32_t& r0, uint32_t& r1,
                                       uint32_t& r2, uint32_t& r3, uint32_t addr) {
    asm volatile("ldmatrix.sync.aligned.m8n8.x4.shared.b16 {%0,%1,%2,%3}, [%4];"
                 : "=r"(r0), "=r"(r1), "=r"(r2), "=r"(r3) : "r"(addr));
}

__device__ __forceinline__ void mma_f16(float* d, const uint32_t* a, const uint32_t* b) {
    asm volatile(
        "mma.sync.aligned.m16n8k16.row.col.f32.f16.f16.f32 "
        "{%0,%1,%2,%3}, {%4,%5,%6,%7}, {%8,%9}, {%0,%1,%2,%3};"
        : "+f"(d[0]), "+f"(d[1]), "+f"(d[2]), "+f"(d[3])
        : "r"(a[0]), "r"(a[1]), "r"(a[2]), "r"(a[3]), "r"(b[0]), "r"(b[1]));
}

__device__ __forceinline__ void cp16(uint32_t dst, const void* src) {
    asm volatile("cp.async.ca.shared.global [%0], [%1], 16;" :: "r"(dst), "l"(src));
}

// ============================================================
// 0) weight prep: transpose + fp16 hi/lo split
// ============================================================
__global__ void prep_w(const float* __restrict__ W, __half* __restrict__ Th,
                       __half* __restrict__ Tl, int K, int N)
{
    int idx = blockIdx.x * 256 + threadIdx.x;
    if (idx >= K * N) return;
    int n = idx / K, k = idx - n * K;
    float v = __ldg(W + (size_t)k * N + n);
    __half h = __float2half_rn(v);
    Th[idx] = h;
    Tl[idx] = __float2half_rn(v - __half2float(h));
}

// ============================================================
// 1) LayerNorm (+ optional shift-roll + window partition), fp16 out
// ============================================================
template<bool WINDOW>
__global__ void ln_kernel(const float* __restrict__ x,
                          const float* __restrict__ gamma,
                          const float* __restrict__ beta,
                          __half* __restrict__ oh)
{
    int r = blockIdx.x;
    size_t src;
    if (WINDOW) {
        int bw = r / 49, l = r % 49;
        int b = bw >> 6, w = bw & 63;
        int i = (w >> 3) * 7 + l / 7;
        int j = (w & 7)  * 7 + l % 7;
        int si = (i + 3) % 56;
        int sj = (j + 3) % 56;
        src = ((size_t)b * 3136 + si * 56 + sj) * 384;
    } else {
        src = (size_t)r * 384;
    }
    int t = threadIdx.x;
    float v0 = x[src + t];
    float v1 = x[src + t + 128];
    float v2 = x[src + t + 256];
    float s  = v0 + v1 + v2;
    float sq = v0 * v0 + v1 * v1 + v2 * v2;
    #pragma unroll
    for (int o = 16; o > 0; o >>= 1) {
        s  += __shfl_xor_sync(0xffffffffu, s,  o);
        sq += __shfl_xor_sync(0xffffffffu, sq, o);
    }
    __shared__ float sa[4], sb[4];
    int wi = t >> 5;
    if ((t & 31) == 0) { sa[wi] = s; sb[wi] = sq; }
    __syncthreads();
    s  = sa[0] + sa[1] + sa[2] + sa[3];
    sq = sb[0] + sb[1] + sb[2] + sb[3];
    float mu  = s  * (1.0f / 384.0f);
    float var = sq * (1.0f / 384.0f) - mu * mu;
    float inv = rsqrtf(var + 1e-3f);
    size_t o0 = (size_t)r * 384;
    oh[o0 + t]       = __float2half_rn((v0 - mu) * inv * gamma[t]       + beta[t]);
    oh[o0 + t + 128] = __float2half_rn((v1 - mu) * inv * gamma[t + 128] + beta[t + 128]);
    oh[o0 + t + 256] = __float2half_rn((v2 - mu) * inv * gamma[t + 256] + beta[t + 256]);
}

// ============================================================
// 2) mma.sync fp16 2-term GEMM, cp.async 2-stage pipeline.
//    C = act(A @ (Wh+Wl)^T + bias); A fp16 [M,K]; W fp16 [N,K] hi/lo.
//    CTA 128x128, BK=32, 8 warps (4m x 2n), warp 32x64.
//    MODE 1: fp32 out TRANSPOSED [N][Mtot] + gelu (smem-staged)
//    MODE 2: fp16 out + gelu
//    MODE 3: fp32 out + residual (row-major)
//    MODE 4: gelu + window-reverse scatter + residual (x2 = x + gelu(..))
// ============================================================
#define STAGE_BYTES 30720   // 3 buffers x 128 rows x 80B
#define GSMEM (2 * STAGE_BYTES)

template<int MODE>
__global__ __launch_bounds__(256)
void tc_gemm(const __half* __restrict__ A_g,
             const __half* __restrict__ Bh,
             const __half* __restrict__ Bl,
             const float* __restrict__ bias, const float* __restrict__ R,
             float* __restrict__ C, __half* __restrict__ Ch,
             int K, int N, int Mtot)
{
    extern __shared__ __align__(16) unsigned char dsm[];
    uint32_t smemBase = smem_u32(dsm);

    int tid  = threadIdx.x;
    int wid  = tid >> 5;
    int lane = tid & 31;
    int m0 = blockIdx.y * 128;
    int n0 = blockIdx.x * 128;
    int mw = (wid >> 1) * 32;
    int nw = (wid & 1)  * 64;

    float acc[2][8][4];
    #pragma unroll
    for (int i = 0; i < 2; i++)
        #pragma unroll
        for (int j = 0; j < 8; j++)
            #pragma unroll
            for (int q = 0; q < 4; q++) acc[i][j][q] = 0.0f;

    uint32_t aOff = (uint32_t)((mw + (lane & 15)) * 80 + ((lane >> 4) << 4));
    uint32_t bOff = (uint32_t)((nw + ((lane >> 4) << 3) + (lane & 7)) * 80 + (((lane >> 3) & 1) << 4));

    int ntiles = K >> 5;

    auto load_stage = [&](int s, int k0) {
        uint32_t sb = smemBase + s * STAGE_BYTES;
        #pragma unroll
        for (int i = 0; i < 2; i++) {
            int idx = tid + (i << 8);         // 0..511
            int row = idx >> 2, q = idx & 3;
            uint32_t d = (uint32_t)(row * 80 + (q << 4));
            cp16(sb + d,         A_g + (size_t)(m0 + row) * K + k0 + (q << 3));
            size_t gb = (size_t)(n0 + row) * K + k0 + (q << 3);
            cp16(sb + 10240 + d, Bh + gb);
            cp16(sb + 20480 + d, Bl + gb);
        }
    };

    load_stage(0, 0);
    asm volatile("cp.async.commit_group;" ::: "memory");

    for (int t = 0; t < ntiles; t++) {
        if (t + 1 < ntiles) {
            load_stage((t + 1) & 1, (t + 1) << 5);
            asm volatile("cp.async.commit_group;" ::: "memory");
            asm volatile("cp.async.wait_group 1;" ::: "memory");
        } else {
            asm volatile("cp.async.wait_group 0;" ::: "memory");
        }
        __syncthreads();

        uint32_t sb = smemBase + (t & 1) * STAGE_BYTES;
        #pragma unroll
        for (int s = 0; s < 2; s++) {
            uint32_t ko = (uint32_t)(s << 5);   // 16 fp16 = 32B
            uint32_t af[2][4], bh[8][2], bl[8][2];
            #pragma unroll
            for (int mt = 0; mt < 2; mt++)
                ldm_x4(af[mt][0], af[mt][1], af[mt][2], af[mt][3],
                       sb + aOff + mt * (16 * 80) + ko);
            #pragma unroll
            for (int np = 0; np < 4; np++) {
                ldm_x4(bh[2 * np][0], bh[2 * np][1], bh[2 * np + 1][0], bh[2 * np + 1][1],
                       sb + 10240 + bOff + np * (16 * 80) + ko);
                ldm_x4(bl[2 * np][0], bl[2 * np][1], bl[2 * np + 1][0], bl[2 * np + 1][1],
                       sb + 20480 + bOff + np * (16 * 80) + ko);
            }
            #pragma unroll
            for (int mt = 0; mt < 2; mt++)
                #pragma unroll
                for (int nt = 0; nt < 8; nt++) {
                    mma_f16(acc[mt][nt], af[mt], bh[nt]);
                    mma_f16(acc[mt][nt], af[mt], bl[nt]);
                }
        }
        __syncthreads();
    }

    // ---- epilogue ----
    if (MODE == 1) {
        float* st = (float*)dsm;   // [64][132]
        #pragma unroll
        for (int p = 0; p < 2; p++) {
            if ((wid & 1) == p) {
                int mL = mw + (lane >> 2);
                int nL = (lane & 3) << 1;
                #pragma unroll
                for (int mt = 0; mt < 2; mt++)
                    #pragma unroll
                    for (int nt = 0; nt < 8; nt++) {
                        int n = nL + nt * 8;
                        float b0 = __ldg(bias + n0 + p * 64 + n);
                        float b1 = __ldg(bias + n0 + p * 64 + n + 1);
                        #pragma unroll
                        for (int hf = 0; hf < 2; hf++) {
                            int m = mL + mt * 16 + hf * 8;
                            st[n * 132 + m]       = gelu_f(acc[mt][nt][hf * 2 + 0] + b0);
                            st[(n + 1) * 132 + m] = gelu_f(acc[mt][nt][hf * 2 + 1] + b1);
                        }
                    }
            }
            __syncthreads();
            #pragma unroll
            for (int i = 0; i < 8; i++) {
                int idx = tid + (i << 8);     // 0..2047
                int n = idx >> 5, mq = idx & 31;
                float4 v = *(float4*)&st[n * 132 + (mq << 2)];
                *(float4*)(C + (size_t)(n0 + p * 64 + n) * Mtot + m0 + (mq << 2)) = v;
            }
            __syncthreads();
        }
        return;
    }

    int mrow = m0 + mw + (lane >> 2);
    int ncol = n0 + nw + ((lane & 3) << 1);
    #pragma unroll
    for (int mt = 0; mt < 2; mt++) {
        #pragma unroll
        for (int hf = 0; hf < 2; hf++) {
            int m = mrow + mt * 16 + hf * 8;
            size_t rowbase;
            if (MODE == 4) {
                // inverse window map: row (bw,l) -> token t
                int bw = m / 49, l = m - bw * 49;
                int b = bw >> 6, w = bw & 63;
                int hh = (w >> 3) * 7 + l / 7;
                int ww = (w & 7)  * 7 + l % 7;
                int i2 = hh + 3; if (i2 >= 56) i2 -= 56;
                int j2 = ww + 3; if (j2 >= 56) j2 -= 56;
                rowbase = ((size_t)b * 3136 + i2 * 56 + j2) * 384;
            } else {
                rowbase = (size_t)m * N;
            }
            #pragma unroll
            for (int nt = 0; nt < 8; nt++) {
                int n = ncol + nt * 8;
                float v0 = acc[mt][nt][hf * 2 + 0] + __ldg(bias + n);
                float v1 = acc[mt][nt][hf * 2 + 1] + __ldg(bias + n + 1);
                size_t off = rowbase + n;
                if (MODE == 2) {
                    v0 = gelu_f(v0); v1 = gelu_f(v1);
                    *(__half2*)(Ch + off) = __halves2half2(__float2half_rn(v0),
                                                           __float2half_rn(v1));
                } else if (MODE == 3) {
                    float2 rv = *(const float2*)(R + off);
                    float2 o; o.x = v0 + rv.x; o.y = v1 + rv.y;
                    *(float2*)(C + off) = o;
                } else { // MODE 4
                    float2 rv = *(const float2*)(R + off);
                    float2 o; o.x = gelu_f(v0) + rv.x; o.y = gelu_f(v1) + rv.y;
                    *(float2*)(C + off) = o;
                }
            }
        }
    }
}

// ============================================================
// 3) Fused windowed attention — coalesced gather from qkvT.
// ============================================================
__global__ __launch_bounds__(256)
void attn_kernel(const float* __restrict__ qkvT, const float* __restrict__ bt,
                 __half* __restrict__ oh)
{
    __shared__ float sQ[1568], sK[1568], sV[1568];
    __shared__ float sS[2401];
    __shared__ int   lab[49];
    int h  = blockIdx.x;
    int bp = blockIdx.y;
    int tid = threadIdx.x;
    size_t base = (size_t)bp * 18816 + h * 1568;

    for (int idx = tid; idx < 1568; idx += 256) {
        sQ[idx] = qkvT[base + idx];
        sK[idx] = qkvT[base + FLATQ + idx];
        sV[idx] = qkvT[base + 2 * (size_t)FLATQ + idx];
    }
    if (tid < 49) {
        int w = bp & 63;
        int i = (w >> 3) * 7 + tid / 7;
        int j = (w & 7)  * 7 + tid % 7;
        int ri = (i < 7) ? 0 : (i < 10) ? 1 : (i >= 53) ? 2 : 3;
        int cj = (j < 7) ? 0 : (j < 10) ? 1 : (j >= 53) ? 2 : 3;
        lab[tid] = (ri < 3 && cj < 3) ? ri * 3 + cj : 0;
    }
    __syncthreads();

    for (int p = tid; p < 2401; p += 256) {
        int l = p / 49, m = p - l * 49;
        float acc = 0.0f;
        #pragma unroll
        for (int c = 0; c < 32; c++) acc += sQ[l * 32 + c] * sK[m * 32 + c];
        int rel = 13 * ((m % 7 - l % 7 + 6) + (m / 7 - l / 7 + 6));
        acc += bt[rel * 12 + h];
        if (lab[l] != lab[m]) acc -= 100.0f;
        sS[p] = acc;
    }
    __syncthreads();

    if (tid < 49) {
        float mx = -1e30f;
        #pragma unroll 7
        for (int m = 0; m < 49; m++) mx = fmaxf(mx, sS[tid * 49 + m]);
        float sum = 0.0f;
        #pragma unroll 7
        for (int m = 0; m < 49; m++) {
            float e = expf(sS[tid * 49 + m] - mx);
            sS[tid * 49 + m] = e;
            sum += e;
        }
        float inv = 1.0f / sum;
        #pragma unroll 7
        for (int m = 0; m < 49; m++) sS[tid * 49 + m] *= inv;
    }
    __syncthreads();

    for (int p = tid; p < 1568; p += 256) {
        int l = p >> 5, c = p & 31;
        float acc = 0.0f;
        #pragma unroll 7
        for (int m = 0; m < 49; m++) acc += sS[l * 49 + m] * sV[m * 32 + c];
        oh[((size_t)bp * 49 + l) * 384 + h * 32 + c] = __float2half_rn(acc);
    }
}

// ============================================================
extern "C" void kernel_launch(void* const* d_in, const int* in_sizes, int n_in,
                              void* d_out, int out_size)
{
    (void)in_sizes; (void)n_in; (void)out_size;
    const float* x     = (const float*)d_in[0];
    const float* gamma = (const float*)d_in[1];
    const float* beta  = (const float*)d_in[2];
    const float* w_qkv = (const float*)d_in[3];
    const float* b_qkv = (const float*)d_in[4];
    const float* bt    = (const float*)d_in[5];
    const float* w_att = (const float*)d_in[6];
    const float* b_att = (const float*)d_in[7];
    const float* w_fc1 = (const float*)d_in[8];
    const float* b_fc1 = (const float*)d_in[9];
    const float* w_fc2 = (const float*)d_in[10];
    const float* b_fc2 = (const float*)d_in[11];
    float* out = (float*)d_out;

    __half *lnh, *atth, *fc1h;
    float *qkvT, *x2;
    cudaGetSymbolAddress((void**)&lnh,  g_lnh);
    cudaGetSymbolAddress((void**)&qkvT, g_qkvT);
    cudaGetSymbolAddress((void**)&atth, g_atth);
    cudaGetSymbolAddress((void**)&x2,   g_x2);
    cudaGetSymbolAddress((void**)&fc1h, g_fc1h);

    __half *wqh, *wql, *wah, *wal, *w1h, *w1l, *w2h, *w2l;
    cudaGetSymbolAddress((void**)&wqh, g_wqkv_h);
    cudaGetSymbolAddress((void**)&wql, g_wqkv_l);
    cudaGetSymbolAddress((void**)&wah, g_watt_h);
    cudaGetSymbolAddress((void**)&wal, g_watt_l);
    cudaGetSymbolAddress((void**)&w1h, g_wfc1_h);
    cudaGetSymbolAddress((void**)&w1l, g_wfc1_l);
    cudaGetSymbolAddress((void**)&w2h, g_wfc2_h);
    cudaGetSymbolAddress((void**)&w2l, g_wfc2_l);

    cudaFuncSetAttribute(tc_gemm<1>, cudaFuncAttributeMaxDynamicSharedMemorySize, GSMEM);
    cudaFuncSetAttribute(tc_gemm<2>, cudaFuncAttributeMaxDynamicSharedMemorySize, GSMEM);
    cudaFuncSetAttribute(tc_gemm<3>, cudaFuncAttributeMaxDynamicSharedMemorySize, GSMEM);
    cudaFuncSetAttribute(tc_gemm<4>, cudaFuncAttributeMaxDynamicSharedMemorySize, GSMEM);

    // weight prep
    prep_w<<<(384 * 1152 + 255) / 256, 256>>>(w_qkv, wqh, wql, 384, 1152);
    prep_w<<<(384 * 384  + 255) / 256, 256>>>(w_att, wah, wal, 384, 384);
    prep_w<<<(384 * 1536 + 255) / 256, 256>>>(w_fc1, w1h, w1l, 384, 1536);
    prep_w<<<(1536 * 384 + 255) / 256, 256>>>(w_fc2, w2h, w2l, 1536, 384);

    // attention branch
    ln_kernel<true><<<TOK, 128>>>(x, gamma, beta, lnh);
    tc_gemm<1><<<dim3(9, 784), 256, GSMEM>>>(lnh, wqh, wql, b_qkv, nullptr,
                                             qkvT, nullptr, 384, 1152, TOK);
    attn_kernel<<<dim3(12, NWIN), 256>>>(qkvT, bt, atth);
    tc_gemm<4><<<dim3(3, 784), 256, GSMEM>>>(atth, wah, wal, b_att, x,
                                             x2, nullptr, 384, 384, TOK);

    // MLP branch
    ln_kernel<false><<<TOK, 128>>>(x2, gamma, beta, lnh);
    tc_gemm<2><<<dim3(12, 784), 256, GSMEM>>>(lnh, w1h, w1l, b_fc1, nullptr,
                                              nullptr, fc1h, 384, 1536, TOK);
    tc_gemm<3><<<dim3(3, 784), 256, GSMEM>>>(fc1h, w2h, w2l, b_fc2, x2,
                                             out, nullptr, 1536, 384, TOK);
}

// round 13
// speedup vs baseline: 2.6760x; 1.1829x over previous
#include <cuda_runtime.h>
#include <cuda_fp16.h>
#include <math.h>
#include <stdint.h>

// ---------------- problem constants ----------------
#define TOK   100352          // 32 * 3136 tokens
#define NWIN  2048            // 32 * 64 windows (b' dim)
#define FLATQ 38535168        // 384 * 100352 (q/k/v channel-slice stride in flat space)

// ---------------- scratch (device globals; no allocations) ----------------
__device__ __half g_lnh [(size_t)TOK * 384];     // LN out (fp16)
__device__ float  g_qkvT[(size_t)1152 * TOK];    // gelu(qkv) TRANSPOSED [col][tok]
__device__ __half g_atth[(size_t)TOK * 384];     // attn out (fp16)
__device__ float  g_x2  [(size_t)TOK * 384];     // x + attention branch
__device__ __half g_fc1h[(size_t)TOK * 1536];    // gelu(fc1) (fp16)

// transposed fp16 weights: Wt[n*K + k] = W[k*N + n]
__device__ __half g_wqkv[1152 * 384];
__device__ __half g_watt[384  * 384];
__device__ __half g_wfc1[1536 * 384];
__device__ __half g_wfc2[384 * 1536];

// ---------------- helpers ----------------
__device__ __forceinline__ float gelu_f(float v) {
    return 0.5f * v * (1.0f + erff(v * 0.70710678118654752f));
}

__device__ __forceinline__ uint32_t smem_u32(const void* p) {
    uint32_t a;
    asm("{ .reg .u64 t; cvta.to.shared.u64 t, %1; cvt.u32.u64 %0, t; }" : "=r"(a) : "l"(p));
    return a;
}

__device__ __forceinline__ void ldm_x4(uint32_t& r0, uint32_t& r1,
                                       uint32_t& r2, uint32_t& r3, uint32_t addr) {
    asm volatile("ldmatrix.sync.aligned.m8n8.x4.shared.b16 {%0,%1,%2,%3}, [%4];"
                 : "=r"(r0), "=r"(r1), "=r"(r2), "=r"(r3) : "r"(addr));
}

__device__ __forceinline__ void mma_f16(float* d, const uint32_t* a, const uint32_t* b) {
    asm volatile(
        "mma.sync.aligned.m16n8k16.row.col.f32.f16.f16.f32 "
        "{%0,%1,%2,%3}, {%4,%5,%6,%7}, {%8,%9}, {%0,%1,%2,%3};"
        : "+f"(d[0]), "+f"(d[1]), "+f"(d[2]), "+f"(d[3])
        : "r"(a[0]), "r"(a[1]), "r"(a[2]), "r"(a[3]), "r"(b[0]), "r"(b[1]));
}

__device__ __forceinline__ void cp16(uint32_t dst, const void* src) {
    asm volatile("cp.async.ca.shared.global [%0], [%1], 16;" :: "r"(dst), "l"(src));
}

// ============================================================
// 0) weight prep: transpose + fp16 round
// ============================================================
__global__ void prep_w(const float* __restrict__ W, __half* __restrict__ T,
                       int K, int N)
{
    int idx = blockIdx.x * 256 + threadIdx.x;
    if (idx >= K * N) return;
    int n = idx / K, k = idx - n * K;
    T[idx] = __float2half_rn(__ldg(W + (size_t)k * N + n));
}

// ============================================================
// 1) LayerNorm (+ optional shift-roll + window partition), fp16 out
// ============================================================
template<bool WINDOW>
__global__ void ln_kernel(const float* __restrict__ x,
                          const float* __restrict__ gamma,
                          const float* __restrict__ beta,
                          __half* __restrict__ oh)
{
    int r = blockIdx.x;
    size_t src;
    if (WINDOW) {
        int bw = r / 49, l = r % 49;
        int b = bw >> 6, w = bw & 63;
        int i = (w >> 3) * 7 + l / 7;
        int j = (w & 7)  * 7 + l % 7;
        int si = (i + 3) % 56;
        int sj = (j + 3) % 56;
        src = ((size_t)b * 3136 + si * 56 + sj) * 384;
    } else {
        src = (size_t)r * 384;
    }
    int t = threadIdx.x;
    float v0 = x[src + t];
    float v1 = x[src + t + 128];
    float v2 = x[src + t + 256];
    float s  = v0 + v1 + v2;
    float sq = v0 * v0 + v1 * v1 + v2 * v2;
    #pragma unroll
    for (int o = 16; o > 0; o >>= 1) {
        s  += __shfl_xor_sync(0xffffffffu, s,  o);
        sq += __shfl_xor_sync(0xffffffffu, sq, o);
    }
    __shared__ float sa[4], sb[4];
    int wi = t >> 5;
    if ((t & 31) == 0) { sa[wi] = s; sb[wi] = sq; }
    __syncthreads();
    s  = sa[0] + sa[1] + sa[2] + sa[3];
    sq = sb[0] + sb[1] + sb[2] + sb[3];
    float mu  = s  * (1.0f / 384.0f);
    float var = sq * (1.0f / 384.0f) - mu * mu;
    float inv = rsqrtf(var + 1e-3f);
    size_t o0 = (size_t)r * 384;
    oh[o0 + t]       = __float2half_rn((v0 - mu) * inv * gamma[t]       + beta[t]);
    oh[o0 + t + 128] = __float2half_rn((v1 - mu) * inv * gamma[t + 128] + beta[t + 128]);
    oh[o0 + t + 256] = __float2half_rn((v2 - mu) * inv * gamma[t + 256] + beta[t + 256]);
}

// ============================================================
// 2) mma.sync fp16 GEMM, cp.async 2-stage pipeline.
//    C = act(A @ W^T + bias); A fp16 [M,K]; W fp16 [N,K].
//    CTA 128x128, BK=32, 8 warps (4m x 2n), warp 32x64.
//    MODE 1: fp32 out TRANSPOSED [N][Mtot] + gelu (smem-staged)
//    MODE 2: fp16 out + gelu
//    MODE 3: fp32 out + residual (row-major)
//    MODE 4: gelu + window-reverse scatter + residual (x2 = x + gelu(..))
// ============================================================
#define STAGE_BYTES 20480   // 2 buffers x 128 rows x 80B
#define GSMEM 40960         // 2 stages (also covers MODE1 epilogue: 64*132*4=33792)

template<int MODE>
__global__ __launch_bounds__(256)
void tc_gemm(const __half* __restrict__ A_g,
             const __half* __restrict__ B_g,
             const float* __restrict__ bias, const float* __restrict__ R,
             float* __restrict__ C, __half* __restrict__ Ch,
             int K, int N, int Mtot)
{
    extern __shared__ __align__(16) unsigned char dsm[];
    uint32_t smemBase = smem_u32(dsm);

    int tid  = threadIdx.x;
    int wid  = tid >> 5;
    int lane = tid & 31;
    int m0 = blockIdx.y * 128;
    int n0 = blockIdx.x * 128;
    int mw = (wid >> 1) * 32;
    int nw = (wid & 1)  * 64;

    float acc[2][8][4];
    #pragma unroll
    for (int i = 0; i < 2; i++)
        #pragma unroll
        for (int j = 0; j < 8; j++)
            #pragma unroll
            for (int q = 0; q < 4; q++) acc[i][j][q] = 0.0f;

    uint32_t aOff = (uint32_t)((mw + (lane & 15)) * 80 + ((lane >> 4) << 4));
    uint32_t bOff = (uint32_t)((nw + ((lane >> 4) << 3) + (lane & 7)) * 80 + (((lane >> 3) & 1) << 4));

    int ntiles = K >> 5;

    auto load_stage = [&](int s, int k0) {
        uint32_t sb = smemBase + s * STAGE_BYTES;
        #pragma unroll
        for (int i = 0; i < 2; i++) {
            int idx = tid + (i << 8);         // 0..511
            int row = idx >> 2, q = idx & 3;
            uint32_t d = (uint32_t)(row * 80 + (q << 4));
            cp16(sb + d,         A_g + (size_t)(m0 + row) * K + k0 + (q << 3));
            cp16(sb + 10240 + d, B_g + (size_t)(n0 + row) * K + k0 + (q << 3));
        }
    };

    load_stage(0, 0);
    asm volatile("cp.async.commit_group;" ::: "memory");

    for (int t = 0; t < ntiles; t++) {
        if (t + 1 < ntiles) {
            load_stage((t + 1) & 1, (t + 1) << 5);
            asm volatile("cp.async.commit_group;" ::: "memory");
            asm volatile("cp.async.wait_group 1;" ::: "memory");
        } else {
            asm volatile("cp.async.wait_group 0;" ::: "memory");
        }
        __syncthreads();

        uint32_t sb = smemBase + (t & 1) * STAGE_BYTES;
        #pragma unroll
        for (int s = 0; s < 2; s++) {
            uint32_t ko = (uint32_t)(s << 5);   // 16 fp16 = 32B
            uint32_t af[2][4], bf[8][2];
            #pragma unroll
            for (int mt = 0; mt < 2; mt++)
                ldm_x4(af[mt][0], af[mt][1], af[mt][2], af[mt][3],
                       sb + aOff + mt * (16 * 80) + ko);
            #pragma unroll
            for (int np = 0; np < 4; np++)
                ldm_x4(bf[2 * np][0], bf[2 * np][1], bf[2 * np + 1][0], bf[2 * np + 1][1],
                       sb + 10240 + bOff + np * (16 * 80) + ko);
            #pragma unroll
            for (int mt = 0; mt < 2; mt++)
                #pragma unroll
                for (int nt = 0; nt < 8; nt++)
                    mma_f16(acc[mt][nt], af[mt], bf[nt]);
        }
        __syncthreads();
    }

    // ---- epilogue ----
    if (MODE == 1) {
        float* st = (float*)dsm;   // [64][132]
        #pragma unroll
        for (int p = 0; p < 2; p++) {
            if ((wid & 1) == p) {
                int mL = mw + (lane >> 2);
                int nL = (lane & 3) << 1;
                #pragma unroll
                for (int mt = 0; mt < 2; mt++)
                    #pragma unroll
                    for (int nt = 0; nt < 8; nt++) {
                        int n = nL + nt * 8;
                        float b0 = __ldg(bias + n0 + p * 64 + n);
                        float b1 = __ldg(bias + n0 + p * 64 + n + 1);
                        #pragma unroll
                        for (int hf = 0; hf < 2; hf++) {
                            int m = mL + mt * 16 + hf * 8;
                            st[n * 132 + m]       = gelu_f(acc[mt][nt][hf * 2 + 0] + b0);
                            st[(n + 1) * 132 + m] = gelu_f(acc[mt][nt][hf * 2 + 1] + b1);
                        }
                    }
            }
            __syncthreads();
            #pragma unroll
            for (int i = 0; i < 8; i++) {
                int idx = tid + (i << 8);     // 0..2047
                int n = idx >> 5, mq = idx & 31;
                float4 v = *(float4*)&st[n * 132 + (mq << 2)];
                *(float4*)(C + (size_t)(n0 + p * 64 + n) * Mtot + m0 + (mq << 2)) = v;
            }
            __syncthreads();
        }
        return;
    }

    int mrow = m0 + mw + (lane >> 2);
    int ncol = n0 + nw + ((lane & 3) << 1);
    #pragma unroll
    for (int mt = 0; mt < 2; mt++) {
        #pragma unroll
        for (int hf = 0; hf < 2; hf++) {
            int m = mrow + mt * 16 + hf * 8;
            size_t rowbase;
            if (MODE == 4) {
                // inverse window map: row (bw,l) -> token
                int bw = m / 49, l = m - bw * 49;
                int b = bw >> 6, w = bw & 63;
                int hh = (w >> 3) * 7 + l / 7;
                int ww = (w & 7)  * 7 + l % 7;
                int i2 = hh + 3; if (i2 >= 56) i2 -= 56;
                int j2 = ww + 3; if (j2 >= 56) j2 -= 56;
                rowbase = ((size_t)b * 3136 + i2 * 56 + j2) * 384;
            } else {
                rowbase = (size_t)m * N;
            }
            #pragma unroll
            for (int nt = 0; nt < 8; nt++) {
                int n = ncol + nt * 8;
                float v0 = acc[mt][nt][hf * 2 + 0] + __ldg(bias + n);
                float v1 = acc[mt][nt][hf * 2 + 1] + __ldg(bias + n + 1);
                size_t off = rowbase + n;
                if (MODE == 2) {
                    v0 = gelu_f(v0); v1 = gelu_f(v1);
                    *(__half2*)(Ch + off) = __halves2half2(__float2half_rn(v0),
                                                           __float2half_rn(v1));
                } else if (MODE == 3) {
                    float2 rv = *(const float2*)(R + off);
                    float2 o; o.x = v0 + rv.x; o.y = v1 + rv.y;
                    *(float2*)(C + off) = o;
                } else { // MODE 4
                    float2 rv = *(const float2*)(R + off);
                    float2 o; o.x = gelu_f(v0) + rv.x; o.y = gelu_f(v1) + rv.y;
                    *(float2*)(C + off) = o;
                }
            }
        }
    }
}

// ============================================================
// 3) Fused windowed attention — coalesced gather from qkvT.
//    Softmax: 4 threads/row, quad-local shuffle mask (no deadlock).
// ============================================================
__global__ __launch_bounds__(256)
void attn_kernel(const float* __restrict__ qkvT, const float* __restrict__ bt,
                 __half* __restrict__ oh)
{
    __shared__ float sQ[1568], sK[1568], sV[1568];
    __shared__ float sS[2401];
    __shared__ int   lab[49];
    int h  = blockIdx.x;
    int bp = blockIdx.y;
    int tid = threadIdx.x;
    size_t base = (size_t)bp * 18816 + h * 1568;

    for (int idx = tid; idx < 1568; idx += 256) {
        sQ[idx] = qkvT[base + idx];
        sK[idx] = qkvT[base + FLATQ + idx];
        sV[idx] = qkvT[base + 2 * (size_t)FLATQ + idx];
    }
    if (tid < 49) {
        int w = bp & 63;
        int i = (w >> 3) * 7 + tid / 7;
        int j = (w & 7)  * 7 + tid % 7;
        int ri = (i < 7) ? 0 : (i < 10) ? 1 : (i >= 53) ? 2 : 3;
        int cj = (j < 7) ? 0 : (j < 10) ? 1 : (j >= 53) ? 2 : 3;
        lab[tid] = (ri < 3 && cj < 3) ? ri * 3 + cj : 0;
    }
    __syncthreads();

    for (int p = tid; p < 2401; p += 256) {
        int l = p / 49, m = p - l * 49;
        float acc = 0.0f;
        #pragma unroll
        for (int c = 0; c < 32; c++) acc += sQ[l * 32 + c] * sK[m * 32 + c];
        int rel = 13 * ((m % 7 - l % 7 + 6) + (m / 7 - l / 7 + 6));
        acc += bt[rel * 12 + h];
        if (lab[l] != lab[m]) acc -= 100.0f;
        sS[p] = acc;
    }
    __syncthreads();

    // softmax: 4 threads per row, shuffles restricted to the quad's own mask
    {
        int row = tid >> 2;
        int sl  = tid & 3;
        if (row < 49) {
            unsigned qmask = 0xFu << ((tid & 31) & ~3);   // this quad's lanes only
            float mx = -1e30f;
            for (int m = sl; m < 49; m += 4) mx = fmaxf(mx, sS[row * 49 + m]);
            mx = fmaxf(mx, __shfl_xor_sync(qmask, mx, 1));
            mx = fmaxf(mx, __shfl_xor_sync(qmask, mx, 2));
            float sum = 0.0f;
            for (int m = sl; m < 49; m += 4) {
                float e = expf(sS[row * 49 + m] - mx);
                sS[row * 49 + m] = e;
                sum += e;
            }
            sum += __shfl_xor_sync(qmask, sum, 1);
            sum += __shfl_xor_sync(qmask, sum, 2);
            float inv = 1.0f / sum;
            for (int m = sl; m < 49; m += 4) sS[row * 49 + m] *= inv;
        }
    }
    __syncthreads();

    for (int p = tid; p < 1568; p += 256) {
        int l = p >> 5, c = p & 31;
        float acc = 0.0f;
        #pragma unroll 7
        for (int m = 0; m < 49; m++) acc += sS[l * 49 + m] * sV[m * 32 + c];
        oh[((size_t)bp * 49 + l) * 384 + h * 32 + c] = __float2half_rn(acc);
    }
}

// ============================================================
extern "C" void kernel_launch(void* const* d_in, const int* in_sizes, int n_in,
                              void* d_out, int out_size)
{
    (void)in_sizes; (void)n_in; (void)out_size;
    const float* x     = (const float*)d_in[0];
    const float* gamma = (const float*)d_in[1];
    const float* beta  = (const float*)d_in[2];
    const float* w_qkv = (const float*)d_in[3];
    const float* b_qkv = (const float*)d_in[4];
    const float* bt    = (const float*)d_in[5];
    const float* w_att = (const float*)d_in[6];
    const float* b_att = (const float*)d_in[7];
    const float* w_fc1 = (const float*)d_in[8];
    const float* b_fc1 = (const float*)d_in[9];
    const float* w_fc2 = (const float*)d_in[10];
    const float* b_fc2 = (const float*)d_in[11];
    float* out = (float*)d_out;

    __half *lnh, *atth, *fc1h;
    float *qkvT, *x2;
    cudaGetSymbolAddress((void**)&lnh,  g_lnh);
    cudaGetSymbolAddress((void**)&qkvT, g_qkvT);
    cudaGetSymbolAddress((void**)&atth, g_atth);
    cudaGetSymbolAddress((void**)&x2,   g_x2);
    cudaGetSymbolAddress((void**)&fc1h, g_fc1h);

    __half *wq, *wa, *w1, *w2;
    cudaGetSymbolAddress((void**)&wq, g_wqkv);
    cudaGetSymbolAddress((void**)&wa, g_watt);
    cudaGetSymbolAddress((void**)&w1, g_wfc1);
    cudaGetSymbolAddress((void**)&w2, g_wfc2);

    cudaFuncSetAttribute(tc_gemm<1>, cudaFuncAttributeMaxDynamicSharedMemorySize, GSMEM);
    cudaFuncSetAttribute(tc_gemm<2>, cudaFuncAttributeMaxDynamicSharedMemorySize, GSMEM);
    cudaFuncSetAttribute(tc_gemm<3>, cudaFuncAttributeMaxDynamicSharedMemorySize, GSMEM);
    cudaFuncSetAttribute(tc_gemm<4>, cudaFuncAttributeMaxDynamicSharedMemorySize, GSMEM);

    // weight prep
    prep_w<<<(384 * 1152 + 255) / 256, 256>>>(w_qkv, wq, 384, 1152);
    prep_w<<<(384 * 384  + 255) / 256, 256>>>(w_att, wa, 384, 384);
    prep_w<<<(384 * 1536 + 255) / 256, 256>>>(w_fc1, w1, 384, 1536);
    prep_w<<<(1536 * 384 + 255) / 256, 256>>>(w_fc2, w2, 1536, 384);

    // attention branch
    ln_kernel<true><<<TOK, 128>>>(x, gamma, beta, lnh);
    tc_gemm<1><<<dim3(9, 784), 256, GSMEM>>>(lnh, wq, b_qkv, nullptr,
                                             qkvT, nullptr, 384, 1152, TOK);
    attn_kernel<<<dim3(12, NWIN), 256>>>(qkvT, bt, atth);
    tc_gemm<4><<<dim3(3, 784), 256, GSMEM>>>(atth, wa, b_att, x,
                                             x2, nullptr, 384, 384, TOK);

    // MLP branch
    ln_kernel<false><<<TOK, 128>>>(x2, gamma, beta, lnh);
    tc_gemm<2><<<dim3(12, 784), 256, GSMEM>>>(lnh, w1, b_fc1, nullptr,
                                              nullptr, fc1h, 384, 1536, TOK);
    tc_gemm<3><<<dim3(3, 784), 256, GSMEM>>>(fc1h, w2, b_fc2, x2,
                                             out, nullptr, 1536, 384, TOK);
}

// round 14
// speedup vs baseline: 4.2502x; 1.5883x over previous
#include <cuda_runtime.h>
#include <cuda_fp16.h>
#include <math.h>
#include <stdint.h>

// ---------------- problem constants ----------------
#define TOK   100352          // 32 * 3136 tokens
#define NWIN  2048            // 32 * 64 windows (b' dim)
#define FLATQ 38535168        // 384 * 100352 (q/k/v channel-slice stride, halves)
#define FLATQ2 19267584       // FLATQ/2 (half2 units)

// ---------------- scratch (device globals; no allocations) ----------------
__device__ __half g_lnh [(size_t)TOK * 384];     // LN out (fp16)
__device__ __half g_qkvT[(size_t)1152 * TOK];    // gelu(qkv) TRANSPOSED [col][tok] fp16
__device__ __half g_atth[(size_t)TOK * 384];     // attn out (fp16)
__device__ float  g_x2  [(size_t)TOK * 384];     // x + attention branch
__device__ __half g_fc1h[(size_t)TOK * 1536];    // gelu(fc1) (fp16)

// transposed fp16 weights: Wt[n*K + k] = W[k*N + n]
__device__ __half g_wqkv[1152 * 384];
__device__ __half g_watt[384  * 384];
__device__ __half g_wfc1[1536 * 384];
__device__ __half g_wfc2[384 * 1536];

// ---------------- helpers ----------------
__device__ __forceinline__ float gelu_f(float v) {
    return 0.5f * v * (1.0f + erff(v * 0.70710678118654752f));
}

__device__ __forceinline__ uint32_t smem_u32(const void* p) {
    uint32_t a;
    asm("{ .reg .u64 t; cvta.to.shared.u64 t, %1; cvt.u32.u64 %0, t; }" : "=r"(a) : "l"(p));
    return a;
}

__device__ __forceinline__ void ldm_x4(uint32_t& r0, uint32_t& r1,
                                       uint32_t& r2, uint32_t& r3, uint32_t addr) {
    asm volatile("ldmatrix.sync.aligned.m8n8.x4.shared.b16 {%0,%1,%2,%3}, [%4];"
                 : "=r"(r0), "=r"(r1), "=r"(r2), "=r"(r3) : "r"(addr));
}

__device__ __forceinline__ void mma_f16(float* d, const uint32_t* a, const uint32_t* b) {
    asm volatile(
        "mma.sync.aligned.m16n8k16.row.col.f32.f16.f16.f32 "
        "{%0,%1,%2,%3}, {%4,%5,%6,%7}, {%8,%9}, {%0,%1,%2,%3};"
        : "+f"(d[0]), "+f"(d[1]), "+f"(d[2]), "+f"(d[3])
        : "r"(a[0]), "r"(a[1]), "r"(a[2]), "r"(a[3]), "r"(b[0]), "r"(b[1]));
}

__device__ __forceinline__ void cp16(uint32_t dst, const void* src) {
    asm volatile("cp.async.ca.shared.global [%0], [%1], 16;" :: "r"(dst), "l"(src));
}

// ============================================================
// 0) weight prep: transpose + fp16 round
// ============================================================
__global__ void prep_w(const float* __restrict__ W, __half* __restrict__ T,
                       int K, int N)
{
    int idx = blockIdx.x * 256 + threadIdx.x;
    if (idx >= K * N) return;
    int n = idx / K, k = idx - n * K;
    T[idx] = __float2half_rn(__ldg(W + (size_t)k * N + n));
}

// ============================================================
// 1) LayerNorm (+ optional shift-roll + window partition), fp16 out
// ============================================================
template<bool WINDOW>
__global__ void ln_kernel(const float* __restrict__ x,
                          const float* __restrict__ gamma,
                          const float* __restrict__ beta,
                          __half* __restrict__ oh)
{
    int r = blockIdx.x;
    size_t src;
    if (WINDOW) {
        int bw = r / 49, l = r % 49;
        int b = bw >> 6, w = bw & 63;
        int i = (w >> 3) * 7 + l / 7;
        int j = (w & 7)  * 7 + l % 7;
        int si = (i + 3) % 56;
        int sj = (j + 3) % 56;
        src = ((size_t)b * 3136 + si * 56 + sj) * 384;
    } else {
        src = (size_t)r * 384;
    }
    int t = threadIdx.x;
    float v0 = x[src + t];
    float v1 = x[src + t + 128];
    float v2 = x[src + t + 256];
    float s  = v0 + v1 + v2;
    float sq = v0 * v0 + v1 * v1 + v2 * v2;
    #pragma unroll
    for (int o = 16; o > 0; o >>= 1) {
        s  += __shfl_xor_sync(0xffffffffu, s,  o);
        sq += __shfl_xor_sync(0xffffffffu, sq, o);
    }
    __shared__ float sa[4], sb[4];
    int wi = t >> 5;
    if ((t & 31) == 0) { sa[wi] = s; sb[wi] = sq; }
    __syncthreads();
    s  = sa[0] + sa[1] + sa[2] + sa[3];
    sq = sb[0] + sb[1] + sb[2] + sb[3];
    float mu  = s  * (1.0f / 384.0f);
    float var = sq * (1.0f / 384.0f) - mu * mu;
    float inv = rsqrtf(var + 1e-3f);
    size_t o0 = (size_t)r * 384;
    oh[o0 + t]       = __float2half_rn((v0 - mu) * inv * gamma[t]       + beta[t]);
    oh[o0 + t + 128] = __float2half_rn((v1 - mu) * inv * gamma[t + 128] + beta[t + 128]);
    oh[o0 + t + 256] = __float2half_rn((v2 - mu) * inv * gamma[t + 256] + beta[t + 256]);
}

// ============================================================
// 2) mma.sync fp16 GEMM, cp.async 2-stage pipeline.
//    MODE 1: fp16 out TRANSPOSED [N][Mtot] + gelu (smem-staged)
//    MODE 2: fp16 out + gelu
//    MODE 3: fp32 out + residual (row-major)
//    MODE 4: gelu + window-reverse scatter + residual (x2 = x + gelu(..))
// ============================================================
#define STAGE_BYTES 20480   // 2 buffers x 128 rows x 80B
#define GSMEM 40960         // 2 stages (also covers MODE1 epilogue: 64*132*4=33792)

template<int MODE>
__global__ __launch_bounds__(256)
void tc_gemm(const __half* __restrict__ A_g,
             const __half* __restrict__ B_g,
             const float* __restrict__ bias, const float* __restrict__ R,
             float* __restrict__ C, __half* __restrict__ Ch,
             int K, int N, int Mtot)
{
    extern __shared__ __align__(16) unsigned char dsm[];
    uint32_t smemBase = smem_u32(dsm);

    int tid  = threadIdx.x;
    int wid  = tid >> 5;
    int lane = tid & 31;
    int m0 = blockIdx.y * 128;
    int n0 = blockIdx.x * 128;
    int mw = (wid >> 1) * 32;
    int nw = (wid & 1)  * 64;

    float acc[2][8][4];
    #pragma unroll
    for (int i = 0; i < 2; i++)
        #pragma unroll
        for (int j = 0; j < 8; j++)
            #pragma unroll
            for (int q = 0; q < 4; q++) acc[i][j][q] = 0.0f;

    uint32_t aOff = (uint32_t)((mw + (lane & 15)) * 80 + ((lane >> 4) << 4));
    uint32_t bOff = (uint32_t)((nw + ((lane >> 4) << 3) + (lane & 7)) * 80 + (((lane >> 3) & 1) << 4));

    int ntiles = K >> 5;

    auto load_stage = [&](int s, int k0) {
        uint32_t sb = smemBase + s * STAGE_BYTES;
        #pragma unroll
        for (int i = 0; i < 2; i++) {
            int idx = tid + (i << 8);         // 0..511
            int row = idx >> 2, q = idx & 3;
            uint32_t d = (uint32_t)(row * 80 + (q << 4));
            cp16(sb + d,         A_g + (size_t)(m0 + row) * K + k0 + (q << 3));
            cp16(sb + 10240 + d, B_g + (size_t)(n0 + row) * K + k0 + (q << 3));
        }
    };

    load_stage(0, 0);
    asm volatile("cp.async.commit_group;" ::: "memory");

    for (int t = 0; t < ntiles; t++) {
        if (t + 1 < ntiles) {
            load_stage((t + 1) & 1, (t + 1) << 5);
            asm volatile("cp.async.commit_group;" ::: "memory");
            asm volatile("cp.async.wait_group 1;" ::: "memory");
        } else {
            asm volatile("cp.async.wait_group 0;" ::: "memory");
        }
        __syncthreads();

        uint32_t sb = smemBase + (t & 1) * STAGE_BYTES;
        #pragma unroll
        for (int s = 0; s < 2; s++) {
            uint32_t ko = (uint32_t)(s << 5);   // 16 fp16 = 32B
            uint32_t af[2][4], bf[8][2];
            #pragma unroll
            for (int mt = 0; mt < 2; mt++)
                ldm_x4(af[mt][0], af[mt][1], af[mt][2], af[mt][3],
                       sb + aOff + mt * (16 * 80) + ko);
            #pragma unroll
            for (int np = 0; np < 4; np++)
                ldm_x4(bf[2 * np][0], bf[2 * np][1], bf[2 * np + 1][0], bf[2 * np + 1][1],
                       sb + 10240 + bOff + np * (16 * 80) + ko);
            #pragma unroll
            for (int mt = 0; mt < 2; mt++)
                #pragma unroll
                for (int nt = 0; nt < 8; nt++)
                    mma_f16(acc[mt][nt], af[mt], bf[nt]);
        }
        __syncthreads();
    }

    // ---- epilogue ----
    if (MODE == 1) {
        // transposed fp16 store via smem staging, two 64-col passes
        float* st = (float*)dsm;   // [64][132]
        #pragma unroll
        for (int p = 0; p < 2; p++) {
            if ((wid & 1) == p) {
                int mL = mw + (lane >> 2);
                int nL = (lane & 3) << 1;
                #pragma unroll
                for (int mt = 0; mt < 2; mt++)
                    #pragma unroll
                    for (int nt = 0; nt < 8; nt++) {
                        int n = nL + nt * 8;
                        float b0 = __ldg(bias + n0 + p * 64 + n);
                        float b1 = __ldg(bias + n0 + p * 64 + n + 1);
                        #pragma unroll
                        for (int hf = 0; hf < 2; hf++) {
                            int m = mL + mt * 16 + hf * 8;
                            st[n * 132 + m]       = gelu_f(acc[mt][nt][hf * 2 + 0] + b0);
                            st[(n + 1) * 132 + m] = gelu_f(acc[mt][nt][hf * 2 + 1] + b1);
                        }
                    }
            }
            __syncthreads();
            #pragma unroll
            for (int i = 0; i < 4; i++) {
                int idx = tid + (i << 8);     // 0..1023
                int n = idx >> 4, mq = idx & 15;   // mq: 8-half chunk
                float4 va = *(float4*)&st[n * 132 + (mq << 3)];
                float4 vb = *(float4*)&st[n * 132 + (mq << 3) + 4];
                __half h8[8];
                h8[0] = __float2half_rn(va.x); h8[1] = __float2half_rn(va.y);
                h8[2] = __float2half_rn(va.z); h8[3] = __float2half_rn(va.w);
                h8[4] = __float2half_rn(vb.x); h8[5] = __float2half_rn(vb.y);
                h8[6] = __float2half_rn(vb.z); h8[7] = __float2half_rn(vb.w);
                *(uint4*)(Ch + (size_t)(n0 + p * 64 + n) * Mtot + m0 + (mq << 3)) =
                    *(uint4*)h8;
            }
            __syncthreads();
        }
        return;
    }

    int mrow = m0 + mw + (lane >> 2);
    int ncol = n0 + nw + ((lane & 3) << 1);
    #pragma unroll
    for (int mt = 0; mt < 2; mt++) {
        #pragma unroll
        for (int hf = 0; hf < 2; hf++) {
            int m = mrow + mt * 16 + hf * 8;
            size_t rowbase;
            if (MODE == 4) {
                // inverse window map: row (bw,l) -> token
                int bw = m / 49, l = m - bw * 49;
                int b = bw >> 6, w = bw & 63;
                int hh = (w >> 3) * 7 + l / 7;
                int ww = (w & 7)  * 7 + l % 7;
                int i2 = hh + 3; if (i2 >= 56) i2 -= 56;
                int j2 = ww + 3; if (j2 >= 56) j2 -= 56;
                rowbase = ((size_t)b * 3136 + i2 * 56 + j2) * 384;
            } else {
                rowbase = (size_t)m * N;
            }
            #pragma unroll
            for (int nt = 0; nt < 8; nt++) {
                int n = ncol + nt * 8;
                float v0 = acc[mt][nt][hf * 2 + 0] + __ldg(bias + n);
                float v1 = acc[mt][nt][hf * 2 + 1] + __ldg(bias + n + 1);
                size_t off = rowbase + n;
                if (MODE == 2) {
                    v0 = gelu_f(v0); v1 = gelu_f(v1);
                    *(__half2*)(Ch + off) = __halves2half2(__float2half_rn(v0),
                                                           __float2half_rn(v1));
                } else if (MODE == 3) {
                    float2 rv = *(const float2*)(R + off);
                    float2 o; o.x = v0 + rv.x; o.y = v1 + rv.y;
                    *(float2*)(C + off) = o;
                } else { // MODE 4
                    float2 rv = *(const float2*)(R + off);
                    float2 o; o.x = gelu_f(v0) + rv.x; o.y = gelu_f(v1) + rv.y;
                    *(float2*)(C + off) = o;
                }
            }
        }
    }
}

// ============================================================
// 3) Fused windowed attention — fp16 gather, half2 smem streams.
// ============================================================
__global__ __launch_bounds__(256)
void attn_kernel(const __half* __restrict__ qkvT, const float* __restrict__ bt,
                 __half* __restrict__ oh)
{
    __shared__ __half2 sQ[784], sK[784], sV[784];   // 49 rows x 16 half2
    __shared__ float sS[2401];
    __shared__ int   lab[49];
    int h  = blockIdx.x;
    int bp = blockIdx.y;
    int tid = threadIdx.x;
    const __half2* qT = (const __half2*)qkvT;
    size_t b2 = (size_t)bp * 9408 + h * 784;   // half2 units

    for (int idx = tid; idx < 784; idx += 256) {
        sQ[idx] = qT[b2 + idx];
        sK[idx] = qT[b2 + FLATQ2 + idx];
        sV[idx] = qT[b2 + 2 * (size_t)FLATQ2 + idx];
    }
    if (tid < 49) {
        int w = bp & 63;
        int i = (w >> 3) * 7 + tid / 7;
        int j = (w & 7)  * 7 + tid % 7;
        int ri = (i < 7) ? 0 : (i < 10) ? 1 : (i >= 53) ? 2 : 3;
        int cj = (j < 7) ? 0 : (j < 10) ? 1 : (j >= 53) ? 2 : 3;
        lab[tid] = (ri < 3 && cj < 3) ? ri * 3 + cj : 0;
    }
    __syncthreads();

    for (int p = tid; p < 2401; p += 256) {
        int l = p / 49, m = p - l * 49;
        const __half2* ql = sQ + l * 16;
        const __half2* kl = sK + m * 16;
        float acc = 0.0f;
        #pragma unroll
        for (int c = 0; c < 16; c++) {
            float2 a = __half22float2(ql[c]);
            float2 b = __half22float2(kl[c]);
            acc += a.x * b.x + a.y * b.y;
        }
        int rel = 13 * ((m % 7 - l % 7 + 6) + (m / 7 - l / 7 + 6));
        acc += bt[rel * 12 + h];
        if (lab[l] != lab[m]) acc -= 100.0f;
        sS[p] = acc;
    }
    __syncthreads();

    // softmax: 4 threads per row, quad-local shuffle mask
    {
        int row = tid >> 2;
        int sl  = tid & 3;
        if (row < 49) {
            unsigned qmask = 0xFu << ((tid & 31) & ~3);
            float mx = -1e30f;
            for (int m = sl; m < 49; m += 4) mx = fmaxf(mx, sS[row * 49 + m]);
            mx = fmaxf(mx, __shfl_xor_sync(qmask, mx, 1));
            mx = fmaxf(mx, __shfl_xor_sync(qmask, mx, 2));
            float sum = 0.0f;
            for (int m = sl; m < 49; m += 4) {
                float e = expf(sS[row * 49 + m] - mx);
                sS[row * 49 + m] = e;
                sum += e;
            }
            sum += __shfl_xor_sync(qmask, sum, 1);
            sum += __shfl_xor_sync(qmask, sum, 2);
            float inv = 1.0f / sum;
            for (int m = sl; m < 49; m += 4) sS[row * 49 + m] *= inv;
        }
    }
    __syncthreads();

    // P @ V: one thread = (l, channel-pair), 784 items
    for (int p = tid; p < 784; p += 256) {
        int l = p >> 4, c2 = p & 15;
        float ax = 0.0f, ay = 0.0f;
        #pragma unroll 7
        for (int m = 0; m < 49; m++) {
            float s = sS[l * 49 + m];
            float2 v = __half22float2(sV[m * 16 + c2]);
            ax += s * v.x; ay += s * v.y;
        }
        size_t off = ((size_t)bp * 49 + l) * 384 + h * 32 + (c2 << 1);
        *(__half2*)(oh + off) = __floats2half2_rn(ax, ay);
    }
}

// ============================================================
extern "C" void kernel_launch(void* const* d_in, const int* in_sizes, int n_in,
                              void* d_out, int out_size)
{
    (void)in_sizes; (void)n_in; (void)out_size;
    const float* x     = (const float*)d_in[0];
    const float* gamma = (const float*)d_in[1];
    const float* beta  = (const float*)d_in[2];
    const float* w_qkv = (const float*)d_in[3];
    const float* b_qkv = (const float*)d_in[4];
    const float* bt    = (const float*)d_in[5];
    const float* w_att = (const float*)d_in[6];
    const float* b_att = (const float*)d_in[7];
    const float* w_fc1 = (const float*)d_in[8];
    const float* b_fc1 = (const float*)d_in[9];
    const float* w_fc2 = (const float*)d_in[10];
    const float* b_fc2 = (const float*)d_in[11];
    float* out = (float*)d_out;

    __half *lnh, *qkvT, *atth, *fc1h;
    float *x2;
    cudaGetSymbolAddress((void**)&lnh,  g_lnh);
    cudaGetSymbolAddress((void**)&qkvT, g_qkvT);
    cudaGetSymbolAddress((void**)&atth, g_atth);
    cudaGetSymbolAddress((void**)&x2,   g_x2);
    cudaGetSymbolAddress((void**)&fc1h, g_fc1h);

    __half *wq, *wa, *w1, *w2;
    cudaGetSymbolAddress((void**)&wq, g_wqkv);
    cudaGetSymbolAddress((void**)&wa, g_watt);
    cudaGetSymbolAddress((void**)&w1, g_wfc1);
    cudaGetSymbolAddress((void**)&w2, g_wfc2);

    cudaFuncSetAttribute(tc_gemm<1>, cudaFuncAttributeMaxDynamicSharedMemorySize, GSMEM);
    cudaFuncSetAttribute(tc_gemm<2>, cudaFuncAttributeMaxDynamicSharedMemorySize, GSMEM);
    cudaFuncSetAttribute(tc_gemm<3>, cudaFuncAttributeMaxDynamicSharedMemorySize, GSMEM);
    cudaFuncSetAttribute(tc_gemm<4>, cudaFuncAttributeMaxDynamicSharedMemorySize, GSMEM);

    // weight prep
    prep_w<<<(384 * 1152 + 255) / 256, 256>>>(w_qkv, wq, 384, 1152);
    prep_w<<<(384 * 384  + 255) / 256, 256>>>(w_att, wa, 384, 384);
    prep_w<<<(384 * 1536 + 255) / 256, 256>>>(w_fc1, w1, 384, 1536);
    prep_w<<<(1536 * 384 + 255) / 256, 256>>>(w_fc2, w2, 1536, 384);

    // attention branch
    ln_kernel<true><<<TOK, 128>>>(x, gamma, beta, lnh);
    tc_gemm<1><<<dim3(9, 784), 256, GSMEM>>>(lnh, wq, b_qkv, nullptr,
                                             nullptr, qkvT, 384, 1152, TOK);
    attn_kernel<<<dim3(12, NWIN), 256>>>(qkvT, bt, atth);
    tc_gemm<4><<<dim3(3, 784), 256, GSMEM>>>(atth, wa, b_att, x,
                                             x2, nullptr, 384, 384, TOK);

    // MLP branch
    ln_kernel<false><<<TOK, 128>>>(x2, gamma, beta, lnh);
    tc_gemm<2><<<dim3(12, 784), 256, GSMEM>>>(lnh, w1, b_fc1, nullptr,
                                              nullptr, fc1h, 384, 1536, TOK);
    tc_gemm<3><<<dim3(3, 784), 256, GSMEM>>>(fc1h, w2, b_fc2, x2,
                                             out, nullptr, 1536, 384, TOK);
}

// round 15
// speedup vs baseline: 4.4460x; 1.0461x over previous
#include <cuda_runtime.h>
#include <cuda_fp16.h>
#include <math.h>
#include <stdint.h>

// ---------------- problem constants ----------------
#define TOK   100352          // 32 * 3136 tokens
#define NWIN  2048            // 32 * 64 windows (b' dim)
#define FLATQ2 19267584       // 192 * 100352 (q/k/v channel-slice stride, half2 units)

// ---------------- scratch (device globals; no allocations) ----------------
__device__ __half g_lnh [(size_t)TOK * 384];     // LN out (fp16)
__device__ __half g_qkvT[(size_t)1152 * TOK];    // gelu(qkv) TRANSPOSED [col][tok] fp16
__device__ __half g_atth[(size_t)TOK * 384];     // attn out (fp16)
__device__ float  g_x2  [(size_t)TOK * 384];     // x + attention branch
__device__ __half g_fc1h[(size_t)TOK * 1536];    // gelu(fc1) (fp16)

// transposed fp16 weights: Wt[n*K + k] = W[k*N + n]
__device__ __half g_wqkv[1152 * 384];
__device__ __half g_watt[384  * 384];
__device__ __half g_wfc1[1536 * 384];
__device__ __half g_wfc2[384 * 1536];

// ---------------- helpers ----------------
__device__ __forceinline__ float gelu_f(float v) {
    return 0.5f * v * (1.0f + erff(v * 0.70710678118654752f));
}

__device__ __forceinline__ uint32_t smem_u32(const void* p) {
    uint32_t a;
    asm("{ .reg .u64 t; cvta.to.shared.u64 t, %1; cvt.u32.u64 %0, t; }" : "=r"(a) : "l"(p));
    return a;
}

__device__ __forceinline__ void ldm_x4(uint32_t& r0, uint32_t& r1,
                                       uint32_t& r2, uint32_t& r3, uint32_t addr) {
    asm volatile("ldmatrix.sync.aligned.m8n8.x4.shared.b16 {%0,%1,%2,%3}, [%4];"
                 : "=r"(r0), "=r"(r1), "=r"(r2), "=r"(r3) : "r"(addr));
}

__device__ __forceinline__ void mma_f16(float* d, const uint32_t* a, const uint32_t* b) {
    asm volatile(
        "mma.sync.aligned.m16n8k16.row.col.f32.f16.f16.f32 "
        "{%0,%1,%2,%3}, {%4,%5,%6,%7}, {%8,%9}, {%0,%1,%2,%3};"
        : "+f"(d[0]), "+f"(d[1]), "+f"(d[2]), "+f"(d[3])
        : "r"(a[0]), "r"(a[1]), "r"(a[2]), "r"(a[3]), "r"(b[0]), "r"(b[1]));
}

__device__ __forceinline__ void cp16(uint32_t dst, const void* src) {
    asm volatile("cp.async.ca.shared.global [%0], [%1], 16;" :: "r"(dst), "l"(src));
}

// ============================================================
// 0) weight prep: transpose + fp16 round
// ============================================================
__global__ void prep_w(const float* __restrict__ W, __half* __restrict__ T,
                       int K, int N)
{
    int idx = blockIdx.x * 256 + threadIdx.x;
    if (idx >= K * N) return;
    int n = idx / K, k = idx - n * K;
    T[idx] = __float2half_rn(__ldg(W + (size_t)k * N + n));
}

// ============================================================
// 1) LayerNorm (+ optional shift-roll + window partition), fp16 out
// ============================================================
template<bool WINDOW>
__global__ void ln_kernel(const float* __restrict__ x,
                          const float* __restrict__ gamma,
                          const float* __restrict__ beta,
                          __half* __restrict__ oh)
{
    int r = blockIdx.x;
    size_t src;
    if (WINDOW) {
        int bw = r / 49, l = r % 49;
        int b = bw >> 6, w = bw & 63;
        int i = (w >> 3) * 7 + l / 7;
        int j = (w & 7)  * 7 + l % 7;
        int si = (i + 3) % 56;
        int sj = (j + 3) % 56;
        src = ((size_t)b * 3136 + si * 56 + sj) * 384;
    } else {
        src = (size_t)r * 384;
    }
    int t = threadIdx.x;
    float v0 = x[src + t];
    float v1 = x[src + t + 128];
    float v2 = x[src + t + 256];
    float s  = v0 + v1 + v2;
    float sq = v0 * v0 + v1 * v1 + v2 * v2;
    #pragma unroll
    for (int o = 16; o > 0; o >>= 1) {
        s  += __shfl_xor_sync(0xffffffffu, s,  o);
        sq += __shfl_xor_sync(0xffffffffu, sq, o);
    }
    __shared__ float sa[4], sb[4];
    int wi = t >> 5;
    if ((t & 31) == 0) { sa[wi] = s; sb[wi] = sq; }
    __syncthreads();
    s  = sa[0] + sa[1] + sa[2] + sa[3];
    sq = sb[0] + sb[1] + sb[2] + sb[3];
    float mu  = s  * (1.0f / 384.0f);
    float var = sq * (1.0f / 384.0f) - mu * mu;
    float inv = rsqrtf(var + 1e-3f);
    size_t o0 = (size_t)r * 384;
    oh[o0 + t]       = __float2half_rn((v0 - mu) * inv * gamma[t]       + beta[t]);
    oh[o0 + t + 128] = __float2half_rn((v1 - mu) * inv * gamma[t + 128] + beta[t + 128]);
    oh[o0 + t + 256] = __float2half_rn((v2 - mu) * inv * gamma[t + 256] + beta[t + 256]);
}

// ============================================================
// 2) mma.sync fp16 GEMM, cp.async 3-stage pipeline.
//    MODE 1: fp16 out TRANSPOSED [N][Mtot] + gelu (smem-staged)
//    MODE 2: fp16 out + gelu
//    MODE 3: fp32 out + residual (row-major)
//    MODE 4: gelu + window-reverse scatter + residual (x2 = x + gelu(..))
// ============================================================
#define STAGE_BYTES 20480   // 2 buffers x 128 rows x 80B
#define GSMEM (3 * STAGE_BYTES)   // 61440; MODE1 epilogue needs 33792 (fits)

template<int MODE>
__global__ __launch_bounds__(256)
void tc_gemm(const __half* __restrict__ A_g,
             const __half* __restrict__ B_g,
             const float* __restrict__ bias, const float* __restrict__ R,
             float* __restrict__ C, __half* __restrict__ Ch,
             int K, int N, int Mtot)
{
    extern __shared__ __align__(16) unsigned char dsm[];
    uint32_t smemBase = smem_u32(dsm);

    int tid  = threadIdx.x;
    int wid  = tid >> 5;
    int lane = tid & 31;
    int m0 = blockIdx.y * 128;
    int n0 = blockIdx.x * 128;
    int mw = (wid >> 1) * 32;
    int nw = (wid & 1)  * 64;

    float acc[2][8][4];
    #pragma unroll
    for (int i = 0; i < 2; i++)
        #pragma unroll
        for (int j = 0; j < 8; j++)
            #pragma unroll
            for (int q = 0; q < 4; q++) acc[i][j][q] = 0.0f;

    uint32_t aOff = (uint32_t)((mw + (lane & 15)) * 80 + ((lane >> 4) << 4));
    uint32_t bOff = (uint32_t)((nw + ((lane >> 4) << 3) + (lane & 7)) * 80 + (((lane >> 3) & 1) << 4));

    int ntiles = K >> 5;

    auto load_stage = [&](int s, int k0) {
        uint32_t sb = smemBase + s * STAGE_BYTES;
        #pragma unroll
        for (int i = 0; i < 2; i++) {
            int idx = tid + (i << 8);         // 0..511
            int row = idx >> 2, q = idx & 3;
            uint32_t d = (uint32_t)(row * 80 + (q << 4));
            cp16(sb + d,         A_g + (size_t)(m0 + row) * K + k0 + (q << 3));
            cp16(sb + 10240 + d, B_g + (size_t)(n0 + row) * K + k0 + (q << 3));
        }
    };

    // 3-stage prologue
    load_stage(0, 0);
    asm volatile("cp.async.commit_group;" ::: "memory");
    if (ntiles > 1) {
        load_stage(1, 32);
        asm volatile("cp.async.commit_group;" ::: "memory");
    }

    for (int t = 0; t < ntiles; t++) {
        if (t + 2 < ntiles) {
            load_stage((t + 2) % 3, (t + 2) << 5);
            asm volatile("cp.async.commit_group;" ::: "memory");
            asm volatile("cp.async.wait_group 2;" ::: "memory");
        } else if (t + 1 < ntiles) {
            asm volatile("cp.async.wait_group 1;" ::: "memory");
        } else {
            asm volatile("cp.async.wait_group 0;" ::: "memory");
        }
        __syncthreads();

        uint32_t sb = smemBase + (t % 3) * STAGE_BYTES;
        #pragma unroll
        for (int s = 0; s < 2; s++) {
            uint32_t ko = (uint32_t)(s << 5);   // 16 fp16 = 32B
            uint32_t af[2][4], bf[8][2];
            #pragma unroll
            for (int mt = 0; mt < 2; mt++)
                ldm_x4(af[mt][0], af[mt][1], af[mt][2], af[mt][3],
                       sb + aOff + mt * (16 * 80) + ko);
            #pragma unroll
            for (int np = 0; np < 4; np++)
                ldm_x4(bf[2 * np][0], bf[2 * np][1], bf[2 * np + 1][0], bf[2 * np + 1][1],
                       sb + 10240 + bOff + np * (16 * 80) + ko);
            #pragma unroll
            for (int mt = 0; mt < 2; mt++)
                #pragma unroll
                for (int nt = 0; nt < 8; nt++)
                    mma_f16(acc[mt][nt], af[mt], bf[nt]);
        }
        __syncthreads();
    }

    // ---- epilogue ----
    if (MODE == 1) {
        // transposed fp16 store via smem staging, two 64-col passes
        float* st = (float*)dsm;   // [64][132]
        #pragma unroll
        for (int p = 0; p < 2; p++) {
            if ((wid & 1) == p) {
                int mL = mw + (lane >> 2);
                int nL = (lane & 3) << 1;
                #pragma unroll
                for (int mt = 0; mt < 2; mt++)
                    #pragma unroll
                    for (int nt = 0; nt < 8; nt++) {
                        int n = nL + nt * 8;
                        float b0 = __ldg(bias + n0 + p * 64 + n);
                        float b1 = __ldg(bias + n0 + p * 64 + n + 1);
                        #pragma unroll
                        for (int hf = 0; hf < 2; hf++) {
                            int m = mL + mt * 16 + hf * 8;
                            st[n * 132 + m]       = gelu_f(acc[mt][nt][hf * 2 + 0] + b0);
                            st[(n + 1) * 132 + m] = gelu_f(acc[mt][nt][hf * 2 + 1] + b1);
                        }
                    }
            }
            __syncthreads();
            #pragma unroll
            for (int i = 0; i < 4; i++) {
                int idx = tid + (i << 8);     // 0..1023
                int n = idx >> 4, mq = idx & 15;   // mq: 8-half chunk
                float4 va = *(float4*)&st[n * 132 + (mq << 3)];
                float4 vb = *(float4*)&st[n * 132 + (mq << 3) + 4];
                __half h8[8];
                h8[0] = __float2half_rn(va.x); h8[1] = __float2half_rn(va.y);
                h8[2] = __float2half_rn(va.z); h8[3] = __float2half_rn(va.w);
                h8[4] = __float2half_rn(vb.x); h8[5] = __float2half_rn(vb.y);
                h8[6] = __float2half_rn(vb.z); h8[7] = __float2half_rn(vb.w);
                *(uint4*)(Ch + (size_t)(n0 + p * 64 + n) * Mtot + m0 + (mq << 3)) =
                    *(uint4*)h8;
            }
            __syncthreads();
        }
        return;
    }

    int mrow = m0 + mw + (lane >> 2);
    int ncol = n0 + nw + ((lane & 3) << 1);
    #pragma unroll
    for (int mt = 0; mt < 2; mt++) {
        #pragma unroll
        for (int hf = 0; hf < 2; hf++) {
            int m = mrow + mt * 16 + hf * 8;
            size_t rowbase;
            if (MODE == 4) {
                // inverse window map: row (bw,l) -> token
                int bw = m / 49, l = m - bw * 49;
                int b = bw >> 6, w = bw & 63;
                int hh = (w >> 3) * 7 + l / 7;
                int ww = (w & 7)  * 7 + l % 7;
                int i2 = hh + 3; if (i2 >= 56) i2 -= 56;
                int j2 = ww + 3; if (j2 >= 56) j2 -= 56;
                rowbase = ((size_t)b * 3136 + i2 * 56 + j2) * 384;
            } else {
                rowbase = (size_t)m * N;
            }
            #pragma unroll
            for (int nt = 0; nt < 8; nt++) {
                int n = ncol + nt * 8;
                float v0 = acc[mt][nt][hf * 2 + 0] + __ldg(bias + n);
                float v1 = acc[mt][nt][hf * 2 + 1] + __ldg(bias + n + 1);
                size_t off = rowbase + n;
                if (MODE == 2) {
                    v0 = gelu_f(v0); v1 = gelu_f(v1);
                    *(__half2*)(Ch + off) = __halves2half2(__float2half_rn(v0),
                                                           __float2half_rn(v1));
                } else if (MODE == 3) {
                    float2 rv = *(const float2*)(R + off);
                    float2 o; o.x = v0 + rv.x; o.y = v1 + rv.y;
                    *(float2*)(C + off) = o;
                } else { // MODE 4
                    float2 rv = *(const float2*)(R + off);
                    float2 o; o.x = gelu_f(v0) + rv.x; o.y = gelu_f(v1) + rv.y;
                    *(float2*)(C + off) = o;
                }
            }
        }
    }
}

// ============================================================
// 3) Fused windowed attention — fp16 gather, half2 smem,
//    K stored TRANSPOSED (stride 51, coprime to 32) so the
//    scores loop is bank-conflict-free across m.
// ============================================================
__global__ __launch_bounds__(256)
void attn_kernel(const __half* __restrict__ qkvT, const float* __restrict__ bt,
                 __half* __restrict__ oh)
{
    __shared__ __half2 sQ[784];          // [l][c2]  49 x 16
    __shared__ __half2 sKT[16 * 51];     // [c2][m]  16 x 49 (pad 51)
    __shared__ __half2 sV[784];          // [m][c2]
    __shared__ float sS[2401];
    __shared__ int   lab[49];
    int h  = blockIdx.x;
    int bp = blockIdx.y;
    int tid = threadIdx.x;
    const __half2* qT = (const __half2*)qkvT;
    size_t b2 = (size_t)bp * 9408 + h * 784;   // half2 units

    for (int idx = tid; idx < 784; idx += 256) {
        int m = idx >> 4, c2 = idx & 15;
        sQ[idx] = qT[b2 + idx];
        sKT[c2 * 51 + m] = qT[b2 + FLATQ2 + idx];
        sV[idx] = qT[b2 + 2 * (size_t)FLATQ2 + idx];
    }
    if (tid < 49) {
        int w = bp & 63;
        int i = (w >> 3) * 7 + tid / 7;
        int j = (w & 7)  * 7 + tid % 7;
        int ri = (i < 7) ? 0 : (i < 10) ? 1 : (i >= 53) ? 2 : 3;
        int cj = (j < 7) ? 0 : (j < 10) ? 1 : (j >= 53) ? 2 : 3;
        lab[tid] = (ri < 3 && cj < 3) ? ri * 3 + cj : 0;
    }
    __syncthreads();

    for (int p = tid; p < 2401; p += 256) {
        int l = p / 49, m = p - l * 49;
        const __half2* ql = sQ + l * 16;
        float acc = 0.0f;
        #pragma unroll
        for (int c = 0; c < 16; c++) {
            float2 a = __half22float2(ql[c]);
            float2 b = __half22float2(sKT[c * 51 + m]);
            acc += a.x * b.x + a.y * b.y;
        }
        int rel = 13 * ((m % 7 - l % 7 + 6) + (m / 7 - l / 7 + 6));
        acc += bt[rel * 12 + h];
        if (lab[l] != lab[m]) acc -= 100.0f;
        sS[p] = acc;
    }
    __syncthreads();

    // softmax: 4 threads per row, quad-local shuffle mask
    {
        int row = tid >> 2;
        int sl  = tid & 3;
        if (row < 49) {
            unsigned qmask = 0xFu << ((tid & 31) & ~3);
            float mx = -1e30f;
            for (int m = sl; m < 49; m += 4) mx = fmaxf(mx, sS[row * 49 + m]);
            mx = fmaxf(mx, __shfl_xor_sync(qmask, mx, 1));
            mx = fmaxf(mx, __shfl_xor_sync(qmask, mx, 2));
            float sum = 0.0f;
            for (int m = sl; m < 49; m += 4) {
                float e = expf(sS[row * 49 + m] - mx);
                sS[row * 49 + m] = e;
                sum += e;
            }
            sum += __shfl_xor_sync(qmask, sum, 1);
            sum += __shfl_xor_sync(qmask, sum, 2);
            float inv = 1.0f / sum;
            for (int m = sl; m < 49; m += 4) sS[row * 49 + m] *= inv;
        }
    }
    __syncthreads();

    // P @ V: one thread = (l, channel-pair), 784 items
    for (int p = tid; p < 784; p += 256) {
        int l = p >> 4, c2 = p & 15;
        float ax = 0.0f, ay = 0.0f;
        #pragma unroll 7
        for (int m = 0; m < 49; m++) {
            float s = sS[l * 49 + m];
            float2 v = __half22float2(sV[m * 16 + c2]);
            ax += s * v.x; ay += s * v.y;
        }
        size_t off = ((size_t)bp * 49 + l) * 384 + h * 32 + (c2 << 1);
        *(__half2*)(oh + off) = __floats2half2_rn(ax, ay);
    }
}

// ============================================================
extern "C" void kernel_launch(void* const* d_in, const int* in_sizes, int n_in,
                              void* d_out, int out_size)
{
    (void)in_sizes; (void)n_in; (void)out_size;
    const float* x     = (const float*)d_in[0];
    const float* gamma = (const float*)d_in[1];
    const float* beta  = (const float*)d_in[2];
    const float* w_qkv = (const float*)d_in[3];
    const float* b_qkv = (const float*)d_in[4];
    const float* bt    = (const float*)d_in[5];
    const float* w_att = (const float*)d_in[6];
    const float* b_att = (const float*)d_in[7];
    const float* w_fc1 = (const float*)d_in[8];
    const float* b_fc1 = (const float*)d_in[9];
    const float* w_fc2 = (const float*)d_in[10];
    const float* b_fc2 = (const float*)d_in[11];
    float* out = (float*)d_out;

    __half *lnh, *qkvT, *atth, *fc1h;
    float *x2;
    cudaGetSymbolAddress((void**)&lnh,  g_lnh);
    cudaGetSymbolAddress((void**)&qkvT, g_qkvT);
    cudaGetSymbolAddress((void**)&atth, g_atth);
    cudaGetSymbolAddress((void**)&x2,   g_x2);
    cudaGetSymbolAddress((void**)&fc1h, g_fc1h);

    __half *wq, *wa, *w1, *w2;
    cudaGetSymbolAddress((void**)&wq, g_wqkv);
    cudaGetSymbolAddress((void**)&wa, g_watt);
    cudaGetSymbolAddress((void**)&w1, g_wfc1);
    cudaGetSymbolAddress((void**)&w2, g_wfc2);

    cudaFuncSetAttribute(tc_gemm<1>, cudaFuncAttributeMaxDynamicSharedMemorySize, GSMEM);
    cudaFuncSetAttribute(tc_gemm<2>, cudaFuncAttributeMaxDynamicSharedMemorySize, GSMEM);
    cudaFuncSetAttribute(tc_gemm<3>, cudaFuncAttributeMaxDynamicSharedMemorySize, GSMEM);
    cudaFuncSetAttribute(tc_gemm<4>, cudaFuncAttributeMaxDynamicSharedMemorySize, GSMEM);

    // weight prep
    prep_w<<<(384 * 1152 + 255) / 256, 256>>>(w_qkv, wq, 384, 1152);
    prep_w<<<(384 * 384  + 255) / 256, 256>>>(w_att, wa, 384, 384);
    prep_w<<<(384 * 1536 + 255) / 256, 256>>>(w_fc1, w1, 384, 1536);
    prep_w<<<(1536 * 384 + 255) / 256, 256>>>(w_fc2, w2, 1536, 384);

    // attention branch
    ln_kernel<true><<<TOK, 128>>>(x, gamma, beta, lnh);
    tc_gemm<1><<<dim3(9, 784), 256, GSMEM>>>(lnh, wq, b_qkv, nullptr,
                                             nullptr, qkvT, 384, 1152, TOK);
    attn_kernel<<<dim3(12, NWIN), 256>>>(qkvT, bt, atth);
    tc_gemm<4><<<dim3(3, 784), 256, GSMEM>>>(atth, wa, b_att, x,
                                             x2, nullptr, 384, 384, TOK);

    // MLP branch
    ln_kernel<false><<<TOK, 128>>>(x2, gamma, beta, lnh);
    tc_gemm<2><<<dim3(12, 784), 256, GSMEM>>>(lnh, w1, b_fc1, nullptr,
                                              nullptr, fc1h, 384, 1536, TOK);
    tc_gemm<3><<<dim3(3, 784), 256, GSMEM>>>(fc1h, w2, b_fc2, x2,
                                             out, nullptr, 1536, 384, TOK);
}